// round 14
// baseline (speedup 1.0000x reference)
#include <cuda_runtime.h>
#include <cuda_fp16.h>
#include <math.h>
#include <stdint.h>

// Problem dims
#define Bc  32
#define Tc  128
#define TYc 64
#define Ec  512
#define Hc  512
#define HHc 256
#define Vc  32000

// ---------------- scratch (__device__ globals; no allocations) ----------------
__device__ __half g_xembh [Bc*Tc*Ec];
__device__ __half g_xbembh[Bc*Tc*Ec];
__device__ __half g_yembh [Bc*TYc*Ec];
__device__ int    g_xback [Bc*Tc];
__device__ float  g_encpre_f[Bc*Tc*4*HHc];
__device__ float  g_encpre_b[Bc*Tc*4*HHc];
__device__ float  g_decpre  [Bc*TYc*4*Hc];
__device__ float  g_ench[2][2*Bc*HHc];   // ping-pong h, [pp][dir*8192 + u*32 + b]
__device__ float  g_hiddens[Bc*Tc*Hc];   // [b][t][fwd|bwd]
__device__ float  g_dech[2][Bc*Hc];      // ping-pong decoder h, [pp][u*32 + b]
__device__ float  g_decc0[Bc*Hc];        // decoder c init, [u*32 + b]
__device__ float  g_outhid[Bc*TYc*2*Hc]; // [b][ty][h|ctx] fp32 (for tail copy)
__device__ __half g_outhidh[Bc*TYc*2*Hc];
__device__ __half g_Wouth [Vc*2*Hc];     // fp16 W_out

// per-block flag barrier state: one 128B line per block, [bar][block*32]
__device__ volatile unsigned g_flags[3][4096];

__device__ __forceinline__ float sigm(float x) { return 1.f / (1.f + expf(-x)); }

__device__ __forceinline__ void gbar(int idx, unsigned phase, int nb, int bid) {
    __syncthreads();
    if (threadIdx.x == 0) {
        __threadfence();
        g_flags[idx][bid * 32] = phase;
    }
    if (threadIdx.x < (unsigned)nb) {
        while (g_flags[idx][threadIdx.x * 32] < phase) { }
    }
    __syncthreads();
}

__device__ __forceinline__ uint32_t smem_u32(const void* p) {
    uint32_t a;
    asm("{ .reg .u64 t; cvta.to.shared.u64 t, %1; cvt.u32.u64 %0, t; }" : "=r"(a) : "l"(p));
    return a;
}
__device__ __forceinline__ void ldsm_x4(uint32_t* r, uint32_t addr) {
    asm volatile("ldmatrix.sync.aligned.m8n8.x4.shared.b16 {%0,%1,%2,%3}, [%4];"
        : "=r"(r[0]), "=r"(r[1]), "=r"(r[2]), "=r"(r[3]) : "r"(addr));
}
__device__ __forceinline__ void ldsm_x2(uint32_t* r, uint32_t addr) {
    asm volatile("ldmatrix.sync.aligned.m8n8.x2.shared.b16 {%0,%1}, [%2];"
        : "=r"(r[0]), "=r"(r[1]) : "r"(addr));
}

#define KH 32
#define PH 40

__device__ __forceinline__ void mma_f16(float* d, const uint32_t* a, const uint32_t* b) {
    asm volatile(
        "mma.sync.aligned.m16n8k16.row.col.f32.f16.f16.f32 "
        "{%0,%1,%2,%3}, {%4,%5,%6,%7}, {%8,%9}, {%0,%1,%2,%3};\n"
        : "+f"(d[0]), "+f"(d[1]), "+f"(d[2]), "+f"(d[3])
        : "r"(a[0]), "r"(a[1]), "r"(a[2]), "r"(a[3]), "r"(b[0]), "r"(b[1]));
}

// ======================================================================
// Variant 1: both operands fp16 (used for projection; W preconverted).
// ======================================================================
__global__ __launch_bounds__(256, 2)
void k_hmma16(const __half* __restrict__ A, const __half* __restrict__ W,
              const float* __restrict__ b1,
              float* __restrict__ C, int M, int N, int K) {
    __shared__ __half sA[2][128 * PH];
    __shared__ __half sB[2][128 * PH];

    const int tid  = threadIdx.x;
    const int wid  = tid >> 5;
    const int lane = tid & 31;
    const int g    = lane >> 2;
    const int t    = lane & 3;
    const int wm   = (wid & 1) * 64;
    const int wn   = (wid >> 1) * 32;
    const int bm   = blockIdx.x * 128;
    const int bn   = blockIdx.y * 128;

    const __half* Ab = A + (size_t)bm * K;
    const __half* Wb = W + (size_t)bn * K;

    const uint32_t aoff = ((wm + (lane & 15)) * PH + (lane >> 4) * 8) * 2;
    const uint32_t boff = ((wn + (lane & 7)) * PH + ((lane >> 3) & 1) * 8) * 2;
    const uint32_t sA0 = smem_u32(&sA[0][0]), sA1 = smem_u32(&sA[1][0]);
    const uint32_t sB0 = smem_u32(&sB[0][0]), sB1 = smem_u32(&sB[1][0]);

#define LOAD_STAGE16(KC0, S) do { \
    _Pragma("unroll") \
    for (int _i = 0; _i < 2; _i++) { \
        int _idx = tid + _i * 256; \
        int _row = _idx >> 2, _seg = _idx & 3; \
        uint32_t _da; \
        asm("{ .reg .u64 t; cvta.to.shared.u64 t, %1; cvt.u32.u64 %0, t; }" \
            : "=r"(_da) : "l"(&sA[S][_row * PH + _seg * 8])); \
        const __half* _sa = Ab + (size_t)_row * K + (KC0) + _seg * 8; \
        asm volatile("cp.async.cg.shared.global [%0], [%1], 16;" :: "r"(_da), "l"(_sa)); \
        uint32_t _db; \
        asm("{ .reg .u64 t; cvta.to.shared.u64 t, %1; cvt.u32.u64 %0, t; }" \
            : "=r"(_db) : "l"(&sB[S][_row * PH + _seg * 8])); \
        const __half* _sb = Wb + (size_t)_row * K + (KC0) + _seg * 8; \
        asm volatile("cp.async.cg.shared.global [%0], [%1], 16;" :: "r"(_db), "l"(_sb)); \
    } \
    asm volatile("cp.async.commit_group;" ::: "memory"); \
} while (0)

    float acc[4][4][4];
#pragma unroll
    for (int i = 0; i < 4; i++)
#pragma unroll
        for (int j = 0; j < 4; j++)
#pragma unroll
            for (int r = 0; r < 4; r++) acc[i][j][r] = 0.f;

    const int NS = K / KH;
    LOAD_STAGE16(0, 0);
    LOAD_STAGE16(KH, 1);

    for (int s = 0; s < NS; s++) {
        if (s + 1 < NS) asm volatile("cp.async.wait_group 1;" ::: "memory");
        else            asm volatile("cp.async.wait_group 0;" ::: "memory");
        __syncthreads();
        const int buf = s & 1;
        const uint32_t pa = (buf ? sA1 : sA0) + aoff;
        const uint32_t pb = (buf ? sB1 : sB0) + boff;
#pragma unroll
        for (int ks = 0; ks < 2; ks++) {
            const uint32_t ko = ks * 32;
            uint32_t af[4][4], bf[4][2];
#pragma unroll
            for (int mt = 0; mt < 4; mt++)
                ldsm_x4(af[mt], pa + mt * (16 * PH * 2) + ko);
#pragma unroll
            for (int nt = 0; nt < 4; nt++)
                ldsm_x2(bf[nt], pb + nt * (8 * PH * 2) + ko);
#pragma unroll
            for (int mt = 0; mt < 4; mt++)
#pragma unroll
                for (int nt = 0; nt < 4; nt++)
                    mma_f16(acc[mt][nt], af[mt], bf[nt]);
        }
        __syncthreads();
        if (s + 2 < NS) LOAD_STAGE16((s + 2) * KH, buf);
    }

#pragma unroll
    for (int nt = 0; nt < 4; nt++) {
        const int n0 = bn + wn + nt * 8 + 2 * t;
        float bb0 = 0.f, bb1 = 0.f;
        if (b1) { bb0 += b1[n0]; bb1 += b1[n0 + 1]; }
#pragma unroll
        for (int mt = 0; mt < 4; mt++) {
            const int m0 = bm + wm + mt * 16 + g;
            float2 v0 = make_float2(acc[mt][nt][0] + bb0, acc[mt][nt][1] + bb1);
            float2 v1 = make_float2(acc[mt][nt][2] + bb0, acc[mt][nt][3] + bb1);
            *(float2*)(C + (size_t)m0 * N + n0)       = v0;
            *(float2*)(C + (size_t)(m0 + 8) * N + n0) = v1;
        }
    }
#undef LOAD_STAGE16
}

// ======================================================================
// Variant 2: W fp32 converted in-kernel (used for small input GEMMs).
// ======================================================================
__device__ __forceinline__ void ldgB(const float* __restrict__ Wb, int K, int kc0,
                                     int tid, float4* r) {
#pragma unroll
    for (int i = 0; i < 2; i++) {
        int idx = tid + i * 256, row = idx >> 2, seg = idx & 3;
        const float4* src = (const float4*)(Wb + (size_t)row * K + kc0 + seg * 8);
        r[i*2 + 0] = src[0];
        r[i*2 + 1] = src[1];
    }
}
__device__ __forceinline__ void stsB(__half* sB, int tid, const float4* r) {
#pragma unroll
    for (int i = 0; i < 2; i++) {
        int idx = tid + i * 256, row = idx >> 2, seg = idx & 3;
        __half2* d = (__half2*)&sB[row * PH + seg * 8];
        d[0] = __floats2half2_rn(r[i*2+0].x, r[i*2+0].y);
        d[1] = __floats2half2_rn(r[i*2+0].z, r[i*2+0].w);
        d[2] = __floats2half2_rn(r[i*2+1].x, r[i*2+1].y);
        d[3] = __floats2half2_rn(r[i*2+1].z, r[i*2+1].w);
    }
}

__global__ __launch_bounds__(256, 2)
void k_hmma_cvt(const __half* __restrict__ A, const float* __restrict__ W,
                const float* __restrict__ b1, const float* __restrict__ b2,
                float* __restrict__ C, int M, int N, int K) {
    __shared__ __half sA[2][128 * PH];
    __shared__ __half sB[2][128 * PH];

    const int tid  = threadIdx.x;
    const int wid  = tid >> 5;
    const int lane = tid & 31;
    const int g    = lane >> 2;
    const int t    = lane & 3;
    const int wm   = (wid & 1) * 64;
    const int wn   = (wid >> 1) * 32;
    const int bm   = blockIdx.x * 128;
    const int bn   = blockIdx.y * 128;

    const __half* Ab = A + (size_t)bm * K;
    const float*  Wb = W + (size_t)bn * K;

    const uint32_t aoff = ((wm + (lane & 15)) * PH + (lane >> 4) * 8) * 2;
    const uint32_t boff = ((wn + (lane & 7)) * PH + ((lane >> 3) & 1) * 8) * 2;
    const uint32_t sA0 = smem_u32(&sA[0][0]), sA1 = smem_u32(&sA[1][0]);
    const uint32_t sB0 = smem_u32(&sB[0][0]), sB1 = smem_u32(&sB[1][0]);

#define LOAD_A(KC0, S) do { \
    _Pragma("unroll") \
    for (int _i = 0; _i < 2; _i++) { \
        int _idx = tid + _i * 256; \
        int _row = _idx >> 2, _seg = _idx & 3; \
        uint32_t _da; \
        asm("{ .reg .u64 t; cvta.to.shared.u64 t, %1; cvt.u32.u64 %0, t; }" \
            : "=r"(_da) : "l"(&sA[S][_row * PH + _seg * 8])); \
        const __half* _sa = Ab + (size_t)_row * K + (KC0) + _seg * 8; \
        asm volatile("cp.async.cg.shared.global [%0], [%1], 16;" :: "r"(_da), "l"(_sa)); \
    } \
    asm volatile("cp.async.commit_group;" ::: "memory"); \
} while (0)

    float acc[4][4][4];
#pragma unroll
    for (int i = 0; i < 4; i++)
#pragma unroll
        for (int j = 0; j < 4; j++)
#pragma unroll
            for (int r = 0; r < 4; r++) acc[i][j][r] = 0.f;

    const int NS = K / KH;
    float4 br[4];
    ldgB(Wb, K, 0, tid, br);
    stsB(&sB[0][0], tid, br);
    ldgB(Wb, K, KH, tid, br);
    LOAD_A(0, 0);
    LOAD_A(KH, 1);

    for (int s = 0; s < NS; s++) {
        if (s + 1 < NS) asm volatile("cp.async.wait_group 1;" ::: "memory");
        else            asm volatile("cp.async.wait_group 0;" ::: "memory");
        __syncthreads();
        const int buf = s & 1;
        const uint32_t pa = (buf ? sA1 : sA0) + aoff;
        const uint32_t pb = (buf ? sB1 : sB0) + boff;
#pragma unroll
        for (int ks = 0; ks < 2; ks++) {
            const uint32_t ko = ks * 32;
            uint32_t af[4][4], bf[4][2];
#pragma unroll
            for (int mt = 0; mt < 4; mt++)
                ldsm_x4(af[mt], pa + mt * (16 * PH * 2) + ko);
#pragma unroll
            for (int nt = 0; nt < 4; nt++)
                ldsm_x2(bf[nt], pb + nt * (8 * PH * 2) + ko);
#pragma unroll
            for (int mt = 0; mt < 4; mt++)
#pragma unroll
                for (int nt = 0; nt < 4; nt++)
                    mma_f16(acc[mt][nt], af[mt], bf[nt]);
        }
        __syncthreads();
        if (s + 1 < NS) stsB(&sB[(s + 1) & 1][0], tid, br);
        if (s + 2 < NS) {
            ldgB(Wb, K, (s + 2) * KH, tid, br);
            LOAD_A((s + 2) * KH, buf);
        }
    }

#pragma unroll
    for (int nt = 0; nt < 4; nt++) {
        const int n0 = bn + wn + nt * 8 + 2 * t;
        float bb0 = 0.f, bb1 = 0.f;
        if (b1) { bb0 += b1[n0]; bb1 += b1[n0 + 1]; }
        if (b2) { bb0 += b2[n0]; bb1 += b2[n0 + 1]; }
#pragma unroll
        for (int mt = 0; mt < 4; mt++) {
            const int m0 = bm + wm + mt * 16 + g;
            float2 v0 = make_float2(acc[mt][nt][0] + bb0, acc[mt][nt][1] + bb1);
            float2 v1 = make_float2(acc[mt][nt][2] + bb0, acc[mt][nt][3] + bb1);
            *(float2*)(C + (size_t)m0 * N + n0)       = v0;
            *(float2*)(C + (size_t)(m0 + 8) * N + n0) = v1;
        }
    }
#undef LOAD_A
}

// ---------------- fp32 -> fp16 conversion (vectorized) ----------------
__global__ void k_f2h(const float* __restrict__ src, __half* __restrict__ dst, int n4) {
    int i = blockIdx.x * blockDim.x + threadIdx.x;
    if (i < n4) {
        float4 v = ((const float4*)src)[i];
        ((__half2*)dst)[i*2 + 0] = __floats2half2_rn(v.x, v.y);
        ((__half2*)dst)[i*2 + 1] = __floats2half2_rn(v.z, v.w);
    }
}

// ---------------- init ----------------
__global__ void k_init() {
    int i = blockIdx.x * blockDim.x + threadIdx.x;
    if (i < 2*2*Bc*HHc) (&g_ench[0][0])[i] = 0.f;
    if (i < Bc*Tc)      g_xback[i] = 0;
    if (i < 3*4096)     ((unsigned*)g_flags)[i] = 0u;
}

// ---------------- pad-aware reversed tokens (parallel) ----------------
__global__ void k_xback(const int* __restrict__ x, const float* __restrict__ mask) {
    const int b = blockIdx.x;
    const int j = threadIdx.x;
    __shared__ float red[4];
    float mv = mask[b*Tc + j];
    for (int o = 16; o; o >>= 1) mv += __shfl_xor_sync(0xffffffffu, mv, o);
    if ((threadIdx.x & 31) == 0) red[threadIdx.x >> 5] = mv;
    __syncthreads();
    float s = red[0] + red[1] + red[2] + red[3];
    int pad = Tc - (int)(s + 0.5f);
    int raw = Tc - 1 - j - pad;
    if (raw >= 1 || j == Tc - 1) {
        int r = raw < 0 ? 0 : raw;
        g_xback[b*Tc + r] = x[b*Tc + j];
    }
}

// ---------------- embedding gather -> fp16 ----------------
__global__ void k_gather_h(const int* __restrict__ idx, const float* __restrict__ embed,
                           __half* __restrict__ out) {
    int row = blockIdx.x;
    int e = threadIdx.x;
    float4 v = ((const float4*)(embed + (size_t)idx[row] * Ec))[e];
    ((__half2*)out)[(size_t)row * (Ec/2) + e*2 + 0] = __floats2half2_rn(v.x, v.y);
    ((__half2*)out)[(size_t)row * (Ec/2) + e*2 + 1] = __floats2half2_rn(v.z, v.w);
}

// ======================================================================
// Persistent encoder scan: 128 blocks (64/dir, 4 units each).
// h staged [b][k] pitch 260 (16B-aligned, conflict-free LDS.128);
// weights [col][k] pitch 260 (warp-uniform float4 broadcast).
// Gate loop: per 4k = 2 LDS.128(w) + 1 LDS.128(h) + 8 FFMA.
// ======================================================================
#define PE 260
__global__ __launch_bounds__(256, 1)
void k_enc_scan(const float* __restrict__ whh_f, const float* __restrict__ whh_b) {
    extern __shared__ float sm[];
    float* wt = sm;                 // [16][PE]
    float* sh = sm + 16*PE;         // [32][PE]
    float* gb = sh + 32*PE;         // [16][33]

    const int tid  = threadIdx.x;
    const int dir  = blockIdx.x >> 6;
    const int ub   = blockIdx.x & 63;
    const int u0   = ub * 4;
    const float* whh = dir ? whh_b : whh_f;
    const float* pre = dir ? g_encpre_b : g_encpre_f;

    for (int j = tid; j < 16*256; j += 256) {
        int col = j >> 8, k = j & 255;
        int gg = col >> 2, uu = col & 3;
        wt[col*PE + k] = whh[(size_t)(gg*HHc + u0 + uu)*HHc + k];
    }

    const int lane = tid & 31;
    const int c0   = (tid >> 5) * 2;     // 2 cols per warp
    const int cb   = tid & 31;
    const int cu   = tid >> 5;
    const bool act = tid < 128;
    const int ug   = dir*HHc + u0 + (act ? cu : 0);
    float creg = 0.f, hsum = 0.f, csum = 0.f;
    __syncthreads();

    for (int t = 0; t < Tc; t++) {
        const float* h_in = &g_ench[t & 1][dir * (Bc*HHc)];
#pragma unroll
        for (int i = 0; i < 8; i++) {
            int idx = tid + i * 256;
            float4 v = __ldcg((const float4*)h_in + idx);
            int j = idx * 4;
            int k = j >> 5, b = j & 31;         // h_in is [k][b]
            sh[(b+0)*PE + k] = v.x; sh[(b+1)*PE + k] = v.y;
            sh[(b+2)*PE + k] = v.z; sh[(b+3)*PE + k] = v.w;
        }
        float pf0 = 0.f, pf1 = 0.f, pf2 = 0.f, pf3 = 0.f;
        if (act) {
            const float* pbt = pre + (size_t)(cb*Tc + t) * (4*HHc) + u0 + cu;
            pf0 = pbt[0*HHc]; pf1 = pbt[1*HHc]; pf2 = pbt[2*HHc]; pf3 = pbt[3*HHc];
        }
        __syncthreads();

        const float4* w4a = (const float4*)&wt[(c0+0)*PE];
        const float4* w4b = (const float4*)&wt[(c0+1)*PE];
        const float4* h4  = (const float4*)&sh[lane*PE];
        float a0 = 0.f, a1 = 0.f;
#pragma unroll 8
        for (int k4 = 0; k4 < 64; k4++) {
            float4 hv = h4[k4];
            float4 w0 = w4a[k4];
            float4 w1 = w4b[k4];
            a0 += w0.x*hv.x + w0.y*hv.y + w0.z*hv.z + w0.w*hv.w;
            a1 += w1.x*hv.x + w1.y*hv.y + w1.z*hv.z + w1.w*hv.w;
        }
        gb[(c0+0)*33 + lane] = a0;
        gb[(c0+1)*33 + lane] = a1;
        __syncthreads();

        if (act) {
            float gi = gb[(0*4 + cu)*33 + cb] + pf0;
            float gf = gb[(1*4 + cu)*33 + cb] + pf1;
            float gc = gb[(2*4 + cu)*33 + cb] + pf2;
            float go = gb[(3*4 + cu)*33 + cb] + pf3;
            creg = sigm(gf) * creg + sigm(gi) * tanhf(gc);
            float hnew = sigm(go) * tanhf(creg);
            hsum += hnew; csum += creg;
            g_ench[(t+1) & 1][dir*(Bc*HHc) + (u0+cu)*32 + cb] = hnew;
            g_hiddens[(size_t)(cb*Tc + t)*Hc + ug] = hnew;
        }
        gbar(dir, (unsigned)(t + 1), 64, ub);
    }

    if (act) {
        g_dech[0][ug*32 + cb] = hsum * (1.0f / Tc);
        g_decc0[ug*32 + cb]   = csum * (1.0f / Tc);
    }
}

// ======================================================================
// Persistent decoder scan: 128 blocks, 4 units each. Same layout, K=512.
// ======================================================================
#define PD 516
__global__ __launch_bounds__(256, 1)
void k_dec_scan(const float* __restrict__ whh) {
    extern __shared__ float sm[];
    float* wt = sm;                 // [16][PD]
    float* sh = sm + 16*PD;         // [32][PD]
    float* gb = sh + 32*PD;         // [16][33]

    const int tid  = threadIdx.x;
    const int u0   = blockIdx.x * 4;

    for (int j = tid; j < 16*512; j += 256) {
        int col = j >> 9, k = j & 511;
        int gg = col >> 2, uu = col & 3;
        wt[col*PD + k] = whh[(size_t)(gg*Hc + u0 + uu)*Hc + k];
    }

    const int lane = tid & 31;
    const int c0   = (tid >> 5) * 2;
    const int cb   = tid & 31;
    const int cu   = tid >> 5;
    const bool act = tid < 128;
    float creg = 0.f;
    __syncthreads();
    if (act) creg = g_decc0[(u0+cu)*32 + cb];

    for (int ty = 0; ty < TYc; ty++) {
        const float* h_in = &g_dech[ty & 1][0];
#pragma unroll
        for (int i = 0; i < 16; i++) {
            int idx = tid + i * 256;
            float4 v = __ldcg((const float4*)h_in + idx);
            int j = idx * 4;
            int k = j >> 5, b = j & 31;
            sh[(b+0)*PD + k] = v.x; sh[(b+1)*PD + k] = v.y;
            sh[(b+2)*PD + k] = v.z; sh[(b+3)*PD + k] = v.w;
        }
        float pf0 = 0.f, pf1 = 0.f, pf2 = 0.f, pf3 = 0.f;
        if (act) {
            const float* pbt = g_decpre + (size_t)(cb*TYc + ty) * (4*Hc) + u0 + cu;
            pf0 = pbt[0*Hc]; pf1 = pbt[1*Hc]; pf2 = pbt[2*Hc]; pf3 = pbt[3*Hc];
        }
        __syncthreads();

        const float4* w4a = (const float4*)&wt[(c0+0)*PD];
        const float4* w4b = (const float4*)&wt[(c0+1)*PD];
        const float4* h4  = (const float4*)&sh[lane*PD];
        float a0 = 0.f, a1 = 0.f;
#pragma unroll 8
        for (int k4 = 0; k4 < 128; k4++) {
            float4 hv = h4[k4];
            float4 w0 = w4a[k4];
            float4 w1 = w4b[k4];
            a0 += w0.x*hv.x + w0.y*hv.y + w0.z*hv.z + w0.w*hv.w;
            a1 += w1.x*hv.x + w1.y*hv.y + w1.z*hv.z + w1.w*hv.w;
        }
        gb[(c0+0)*33 + lane] = a0;
        gb[(c0+1)*33 + lane] = a1;
        __syncthreads();

        if (act) {
            float gi = gb[(0*4 + cu)*33 + cb] + pf0;
            float gf = gb[(1*4 + cu)*33 + cb] + pf1;
            float gc = gb[(2*4 + cu)*33 + cb] + pf2;
            float go = gb[(3*4 + cu)*33 + cb] + pf3;
            creg = sigm(gf) * creg + sigm(gi) * tanhf(gc);
            float hnew = sigm(go) * tanhf(creg);
            g_dech[(ty+1) & 1][(u0+cu)*32 + cb] = hnew;
            size_t oi = (size_t)(cb*TYc + ty)*(2*Hc) + u0 + cu;
            g_outhid[oi]  = hnew;
            g_outhidh[oi] = __float2half(hnew);
        }
        gbar(2, (unsigned)(ty + 1), 128, blockIdx.x);
    }
}

// ---------------- attention, batch-parallel over (b, ty) ----------------
__global__ __launch_bounds__(256, 1)
void k_attn() {
    const int b  = blockIdx.x;
    const int ty = blockIdx.y;
    const float* h = g_outhid + (size_t)(b*TYc + ty)*(2*Hc);
    __shared__ float hs[Hc];
    __shared__ float sc[Tc];
    __shared__ float red[8];
    for (int i = threadIdx.x; i < Hc; i += 256) hs[i] = h[i];
    __syncthreads();

    const int tp = threadIdx.x >> 1;
    const int half = threadIdx.x & 1;
    const float* hid = g_hiddens + (size_t)(b*Tc + tp)*Hc + half*256;
    const float* hq = hs + half*256;
    float s = 0.f;
#pragma unroll 4
    for (int k = 0; k < 256; k += 4) {
        float4 a = *(const float4*)(hid + k);
        float4 c = *(const float4*)(hq + k);
        s += a.x*c.x + a.y*c.y + a.z*c.z + a.w*c.w;
    }
    s += __shfl_down_sync(0xffffffffu, s, 1);
    if (half == 0) sc[tp] = s;
    __syncthreads();

    const int lane = threadIdx.x & 31, wid = threadIdx.x >> 5;
    float v = (threadIdx.x < Tc) ? sc[threadIdx.x] : -1e30f;
    float m = v;
    for (int o = 16; o; o >>= 1) m = fmaxf(m, __shfl_xor_sync(0xffffffffu, m, o));
    if (!lane) red[wid] = m;
    __syncthreads();
    if (!wid) {
        float xx = (lane < 8) ? red[lane] : -1e30f;
        for (int o = 4; o; o >>= 1) xx = fmaxf(xx, __shfl_xor_sync(0xffffffffu, xx, o));
        if (!lane) red[0] = xx;
    }
    __syncthreads();
    m = red[0];
    float e = (threadIdx.x < Tc) ? expf(v - m) : 0.f;
    float ssum = e;
    for (int o = 16; o; o >>= 1) ssum += __shfl_xor_sync(0xffffffffu, ssum, o);
    __syncthreads();
    if (!lane) red[wid] = ssum;
    __syncthreads();
    if (!wid) {
        float xx = (lane < 8) ? red[lane] : 0.f;
        for (int o = 4; o; o >>= 1) xx += __shfl_xor_sync(0xffffffffu, xx, o);
        if (!lane) red[0] = xx;
    }
    __syncthreads();
    float inv = 1.f / red[0];
    if (threadIdx.x < Tc) sc[threadIdx.x] = e * inv;
    __syncthreads();

    float* octx  = g_outhid  + (size_t)(b*TYc + ty)*(2*Hc) + Hc;
    __half* octh = g_outhidh + (size_t)(b*TYc + ty)*(2*Hc) + Hc;
    for (int d = threadIdx.x; d < Hc; d += 256) {
        float a = 0.f;
#pragma unroll 8
        for (int tq = 0; tq < Tc; tq++) a += sc[tq] * g_hiddens[(size_t)(b*Tc + tq)*Hc + d];
        octx[d] = a;
        octh[d] = __float2half(a);
    }
}

// ---------------- in-place log_softmax (online max+sum) ----------------
__global__ __launch_bounds__(256)
void k_logsoftmax(float* __restrict__ out) {
    const int row = blockIdx.x;
    float* p = out + (size_t)row * Vc;
    __shared__ float redm[8], reds[8];
    const int lane = threadIdx.x & 31, wid = threadIdx.x >> 5;

    float m = -1e30f, s = 0.f;
    for (int i = threadIdx.x; i < Vc; i += 256) {
        float v = p[i];
        if (v > m) { s = s * expf(m - v) + 1.f; m = v; }
        else       s += expf(v - m);
    }
    for (int o = 16; o; o >>= 1) {
        float mo = __shfl_xor_sync(0xffffffffu, m, o);
        float so = __shfl_xor_sync(0xffffffffu, s, o);
        float mn = fmaxf(m, mo);
        s = s * expf(m - mn) + so * expf(mo - mn);
        m = mn;
    }
    if (!lane) { redm[wid] = m; reds[wid] = s; }
    __syncthreads();
    if (!wid) {
        float mm = (lane < 8) ? redm[lane] : -1e30f;
        float ss = (lane < 8) ? reds[lane] : 0.f;
        for (int o = 4; o; o >>= 1) {
            float mo = __shfl_xor_sync(0xffffffffu, mm, o);
            float so = __shfl_xor_sync(0xffffffffu, ss, o);
            float mn = fmaxf(mm, mo);
            ss = ss * expf(mm - mn) + so * expf(mo - mn);
            mm = mn;
        }
        if (!lane) { redm[0] = mm; reds[0] = ss; }
    }
    __syncthreads();
    float lse = redm[0] + logf(reds[0]);
    for (int i = threadIdx.x; i < Vc; i += 256) p[i] -= lse;
}

__global__ void k_copy_tail(float* __restrict__ dst) {
    int i = blockIdx.x * blockDim.x + threadIdx.x;
    if (i < Bc*TYc*2*Hc) dst[i] = g_outhid[i];
}

// ---------------- launch ----------------
extern "C" void kernel_launch(void* const* d_in, const int* in_sizes, int n_in,
                              void* d_out, int out_size) {
    (void)in_sizes; (void)n_in;
    const int*   x      = (const int*)  d_in[0];
    const float* xmask  = (const float*)d_in[1];
    const int*   y      = (const int*)  d_in[2];
    const float* embed  = (const float*)d_in[3];
    const float* w_ih_f = (const float*)d_in[4];
    const float* w_hh_f = (const float*)d_in[5];
    const float* b_ih_f = (const float*)d_in[6];
    const float* b_hh_f = (const float*)d_in[7];
    const float* w_ih_b = (const float*)d_in[8];
    const float* w_hh_b = (const float*)d_in[9];
    const float* b_ih_b = (const float*)d_in[10];
    const float* b_hh_b = (const float*)d_in[11];
    const float* w_ih_d = (const float*)d_in[12];
    const float* w_hh_d = (const float*)d_in[13];
    const float* b_ih_d = (const float*)d_in[14];
    const float* b_hh_d = (const float*)d_in[15];
    const float* W_out  = (const float*)d_in[16];
    const float* b_out  = (const float*)d_in[17];
    float* out = (float*)d_out;

    void *p_xembh, *p_xbembh, *p_yembh, *p_pref, *p_preb, *p_decpre, *p_outhid, *p_outhidh, *p_xback, *p_Wo;
    cudaGetSymbolAddress(&p_xembh,  g_xembh);
    cudaGetSymbolAddress(&p_xbembh, g_xbembh);
    cudaGetSymbolAddress(&p_yembh,  g_yembh);
    cudaGetSymbolAddress(&p_pref,   g_encpre_f);
    cudaGetSymbolAddress(&p_preb,   g_encpre_b);
    cudaGetSymbolAddress(&p_decpre, g_decpre);
    cudaGetSymbolAddress(&p_outhid, g_outhid);
    cudaGetSymbolAddress(&p_outhidh,g_outhidh);
    cudaGetSymbolAddress(&p_xback,  g_xback);
    cudaGetSymbolAddress(&p_Wo,     g_Wouth);

    const int ENC_SMEM = (16*PE + 32*PE + 16*33) * 4;   //  52,032 B
    const int DEC_SMEM = (16*PD + 32*PD + 16*33) * 4;   // 101,184 B
    static bool attr_done = false;
    if (!attr_done) {
        cudaFuncSetAttribute(k_enc_scan, cudaFuncAttributeMaxDynamicSharedMemorySize, ENC_SMEM);
        cudaFuncSetAttribute(k_dec_scan, cudaFuncAttributeMaxDynamicSharedMemorySize, DEC_SMEM);
        attr_done = true;
    }

    k_init<<<128, 256>>>();
    k_xback<<<Bc, Tc>>>(x, xmask);

    // W_out -> fp16 once (projection is L2-bound on W; fp16 halves that traffic)
    k_f2h<<<(Vc*2*Hc/4 + 255)/256, 256>>>(W_out, (__half*)p_Wo, Vc*2*Hc/4);

    k_gather_h<<<Bc*Tc, 128>>>(x, embed, (__half*)p_xembh);
    k_gather_h<<<Bc*Tc, 128>>>((const int*)p_xback, embed, (__half*)p_xbembh);
    k_gather_h<<<Bc*TYc, 128>>>(y, embed, (__half*)p_yembh);

    // input-side GEMMs: W fp32 converted in-kernel (W is small; L2 traffic trivial)
    k_hmma_cvt<<<dim3((Bc*Tc)/128, (4*HHc)/128), 256>>>(
        (const __half*)p_xembh,  w_ih_f, b_ih_f, b_hh_f, (float*)p_pref,   Bc*Tc,  4*HHc, Ec);
    k_hmma_cvt<<<dim3((Bc*Tc)/128, (4*HHc)/128), 256>>>(
        (const __half*)p_xbembh, w_ih_b, b_ih_b, b_hh_b, (float*)p_preb,   Bc*Tc,  4*HHc, Ec);
    k_hmma_cvt<<<dim3((Bc*TYc)/128, (4*Hc)/128), 256>>>(
        (const __half*)p_yembh,  w_ih_d, b_ih_d, b_hh_d, (float*)p_decpre, Bc*TYc, 4*Hc,  Ec);

    // persistent scans
    k_enc_scan<<<128, 256, ENC_SMEM>>>(w_hh_f, w_hh_b);
    k_dec_scan<<<128, 256, DEC_SMEM>>>(w_hh_d);

    // attention
    k_attn<<<dim3(Bc, TYc), 256>>>();

    // projection (both operands fp16) + log_softmax
    k_hmma16<<<dim3((Bc*TYc)/128, Vc/128), 256>>>(
        (const __half*)p_outhidh, (const __half*)p_Wo, b_out, out, Bc*TYc, Vc, 2*Hc);
    k_logsoftmax<<<Bc*TYc, 256>>>(out);

    long long need = (long long)Bc*TYc*Vc + (long long)Bc*TYc*2*Hc;
    if ((long long)out_size >= need)
        k_copy_tail<<<(Bc*TYc*2*Hc + 255)/256, 256>>>(out + (size_t)Bc*TYc*Vc);
}

// round 15
// speedup vs baseline: 1.0894x; 1.0894x over previous
#include <cuda_runtime.h>
#include <cuda_fp16.h>
#include <math.h>
#include <stdint.h>

// Problem dims
#define Bc  32
#define Tc  128
#define TYc 64
#define Ec  512
#define Hc  512
#define HHc 256
#define Vc  32000

// ---------------- scratch (__device__ globals; no allocations) ----------------
__device__ __half g_xembh [Bc*Tc*Ec];
__device__ __half g_xbembh[Bc*Tc*Ec];
__device__ __half g_yembh [Bc*TYc*Ec];
__device__ int    g_xback [Bc*Tc];
__device__ float  g_encpre_f[Bc*Tc*4*HHc];
__device__ float  g_encpre_b[Bc*Tc*4*HHc];
__device__ float  g_decpre  [Bc*TYc*4*Hc];
__device__ float  g_ench[2][2*Bc*HHc];   // ping-pong h, [pp][dir*8192 + u*32 + b]
__device__ float  g_hiddens[Bc*Tc*Hc];   // [b][t][fwd|bwd]
__device__ float  g_dech[2][Bc*Hc];      // ping-pong decoder h, [pp][u*32 + b]
__device__ float  g_decc0[Bc*Hc];        // decoder c init, [u*32 + b]
__device__ float  g_outhid[Bc*TYc*2*Hc]; // [b][ty][h|ctx] fp32 (for tail copy)
__device__ __half g_outhidh[Bc*TYc*2*Hc];
// fp16 weight copies
__device__ __half g_wihf_h[4*HHc*Ec];
__device__ __half g_wihb_h[4*HHc*Ec];
__device__ __half g_wihd_h[4*Hc*Ec];
__device__ __half g_Wouth [Vc*2*Hc];

// per-block flag barrier state: one 128B line per block, [bar][block*32]
__device__ volatile unsigned g_flags[3][4096];

__device__ __forceinline__ float sigm(float x) { return 1.f / (1.f + expf(-x)); }

// flag-array grid barrier: arrival = parallel STG (distinct L2 lines),
// wait = thread i polls block i's flag.
__device__ __forceinline__ void gbar(int idx, unsigned phase, int nb, int bid) {
    __syncthreads();
    if (threadIdx.x == 0) {
        __threadfence();
        g_flags[idx][bid * 32] = phase;
    }
    if (threadIdx.x < (unsigned)nb) {
        while (g_flags[idx][threadIdx.x * 32] < phase) { }
    }
    __syncthreads();
}

__device__ __forceinline__ uint32_t smem_u32(const void* p) {
    uint32_t a;
    asm("{ .reg .u64 t; cvta.to.shared.u64 t, %1; cvt.u32.u64 %0, t; }" : "=r"(a) : "l"(p));
    return a;
}
__device__ __forceinline__ void ldsm_x4(uint32_t* r, uint32_t addr) {
    asm volatile("ldmatrix.sync.aligned.m8n8.x4.shared.b16 {%0,%1,%2,%3}, [%4];"
        : "=r"(r[0]), "=r"(r[1]), "=r"(r[2]), "=r"(r[3]) : "r"(addr));
}
__device__ __forceinline__ void ldsm_x2(uint32_t* r, uint32_t addr) {
    asm volatile("ldmatrix.sync.aligned.m8n8.x2.shared.b16 {%0,%1}, [%2];"
        : "=r"(r[0]), "=r"(r[1]) : "r"(addr));
}

#define KH 32
#define PH 40
#define NSTG 3
#define STG_HALVES (128 * PH)          // per array per stage

__device__ __forceinline__ void mma_f16(float* d, const uint32_t* a, const uint32_t* b) {
    asm volatile(
        "mma.sync.aligned.m16n8k16.row.col.f32.f16.f16.f32 "
        "{%0,%1,%2,%3}, {%4,%5,%6,%7}, {%8,%9}, {%0,%1,%2,%3};\n"
        : "+f"(d[0]), "+f"(d[1]), "+f"(d[2]), "+f"(d[3])
        : "r"(a[0]), "r"(a[1]), "r"(a[2]), "r"(a[3]), "r"(b[0]), "r"(b[1]));
}

// ======================================================================
// fp16 mma.sync GEMM: C[M,N] = A[M,K] @ W[N,K]^T (+b1 +b2), fp32 accum.
// CTA 128x128, 8 warps, warp tile 64x32, K-stage 32 halves.
// 3-stage cp.async pipeline, ONE __syncthreads per stage:
//   load of stage s+2 writes buffer (s+2)%3 == (s-1)%3, whose readers all
//   passed the iteration-s barrier -> no second sync needed.
// ======================================================================
__global__ __launch_bounds__(256, 2)
void k_hmma16(const __half* __restrict__ A, const __half* __restrict__ W,
              const float* __restrict__ b1, const float* __restrict__ b2,
              float* __restrict__ C, int M, int N, int K) {
    extern __shared__ __half hsm[];
    __half* sA = hsm;                       // [NSTG][128*PH]
    __half* sB = hsm + NSTG * STG_HALVES;   // [NSTG][128*PH]

    const int tid  = threadIdx.x;
    const int wid  = tid >> 5;
    const int lane = tid & 31;
    const int g    = lane >> 2;
    const int t    = lane & 3;
    const int wm   = (wid & 1) * 64;
    const int wn   = (wid >> 1) * 32;
    const int bm   = blockIdx.x * 128;
    const int bn   = blockIdx.y * 128;

    const __half* Ab = A + (size_t)bm * K;
    const __half* Wb = W + (size_t)bn * K;

    const uint32_t aoff = ((wm + (lane & 15)) * PH + (lane >> 4) * 8) * 2;
    const uint32_t boff = ((wn + (lane & 7)) * PH + ((lane >> 3) & 1) * 8) * 2;
    const uint32_t sAu = smem_u32(sA);
    const uint32_t sBu = smem_u32(sB);

#define LOAD_STAGE(KC0, S) do { \
    _Pragma("unroll") \
    for (int _i = 0; _i < 2; _i++) { \
        int _idx = tid + _i * 256; \
        int _row = _idx >> 2, _seg = _idx & 3; \
        uint32_t _da = sAu + ((S) * STG_HALVES + _row * PH + _seg * 8) * 2; \
        const __half* _sa = Ab + (size_t)_row * K + (KC0) + _seg * 8; \
        asm volatile("cp.async.cg.shared.global [%0], [%1], 16;" :: "r"(_da), "l"(_sa)); \
        uint32_t _db = sBu + ((S) * STG_HALVES + _row * PH + _seg * 8) * 2; \
        const __half* _sb = Wb + (size_t)_row * K + (KC0) + _seg * 8; \
        asm volatile("cp.async.cg.shared.global [%0], [%1], 16;" :: "r"(_db), "l"(_sb)); \
    } \
    asm volatile("cp.async.commit_group;" ::: "memory"); \
} while (0)

    float acc[4][4][4];
#pragma unroll
    for (int i = 0; i < 4; i++)
#pragma unroll
        for (int j = 0; j < 4; j++)
#pragma unroll
            for (int r = 0; r < 4; r++) acc[i][j][r] = 0.f;

    const int NS = K / KH;
    LOAD_STAGE(0, 0);
    LOAD_STAGE(KH, 1);

    int buf = 0;
    for (int s = 0; s < NS; s++) {
        if (s + 1 < NS) asm volatile("cp.async.wait_group 1;" ::: "memory");
        else            asm volatile("cp.async.wait_group 0;" ::: "memory");
        __syncthreads();

        const uint32_t pa = sAu + buf * (STG_HALVES * 2) + aoff;
        const uint32_t pb = sBu + buf * (STG_HALVES * 2) + boff;
#pragma unroll
        for (int ks = 0; ks < 2; ks++) {
            const uint32_t ko = ks * 32;
            uint32_t af[4][4], bf[4][2];
#pragma unroll
            for (int mt = 0; mt < 4; mt++)
                ldsm_x4(af[mt], pa + mt * (16 * PH * 2) + ko);
#pragma unroll
            for (int nt = 0; nt < 4; nt++)
                ldsm_x2(bf[nt], pb + nt * (8 * PH * 2) + ko);
#pragma unroll
            for (int mt = 0; mt < 4; mt++)
#pragma unroll
                for (int nt = 0; nt < 4; nt++)
                    mma_f16(acc[mt][nt], af[mt], bf[nt]);
        }
        if (s + 2 < NS) {
            int nb = buf + 2; if (nb >= NSTG) nb -= NSTG;
            LOAD_STAGE((s + 2) * KH, nb);
        }
        buf = (buf + 1 == NSTG) ? 0 : buf + 1;
    }

    // epilogue: c0=[g][2t], c1=[g][2t+1], c2=[g+8][2t], c3=[g+8][2t+1]
#pragma unroll
    for (int nt = 0; nt < 4; nt++) {
        const int n0 = bn + wn + nt * 8 + 2 * t;
        float bb0 = 0.f, bb1 = 0.f;
        if (b1) { bb0 += b1[n0]; bb1 += b1[n0 + 1]; }
        if (b2) { bb0 += b2[n0]; bb1 += b2[n0 + 1]; }
#pragma unroll
        for (int mt = 0; mt < 4; mt++) {
            const int m0 = bm + wm + mt * 16 + g;
            float2 v0 = make_float2(acc[mt][nt][0] + bb0, acc[mt][nt][1] + bb1);
            float2 v1 = make_float2(acc[mt][nt][2] + bb0, acc[mt][nt][3] + bb1);
            *(float2*)(C + (size_t)m0 * N + n0)       = v0;
            *(float2*)(C + (size_t)(m0 + 8) * N + n0) = v1;
        }
    }
#undef LOAD_STAGE
}

// ---------------- fp32 -> fp16 conversion (vectorized) ----------------
__global__ void k_f2h(const float* __restrict__ src, __half* __restrict__ dst, int n4) {
    int i = blockIdx.x * blockDim.x + threadIdx.x;
    if (i < n4) {
        float4 v = ((const float4*)src)[i];
        ((__half2*)dst)[i*2 + 0] = __floats2half2_rn(v.x, v.y);
        ((__half2*)dst)[i*2 + 1] = __floats2half2_rn(v.z, v.w);
    }
}

// ---------------- init ----------------
__global__ void k_init() {
    int i = blockIdx.x * blockDim.x + threadIdx.x;
    if (i < 2*2*Bc*HHc) (&g_ench[0][0])[i] = 0.f;
    if (i < Bc*Tc)      g_xback[i] = 0;
    if (i < 3*4096)     ((unsigned*)g_flags)[i] = 0u;
}

// ---------------- pad-aware reversed tokens (parallel) ----------------
__global__ void k_xback(const int* __restrict__ x, const float* __restrict__ mask) {
    const int b = blockIdx.x;
    const int j = threadIdx.x;
    __shared__ float red[4];
    float mv = mask[b*Tc + j];
    for (int o = 16; o; o >>= 1) mv += __shfl_xor_sync(0xffffffffu, mv, o);
    if ((threadIdx.x & 31) == 0) red[threadIdx.x >> 5] = mv;
    __syncthreads();
    float s = red[0] + red[1] + red[2] + red[3];
    int pad = Tc - (int)(s + 0.5f);
    int raw = Tc - 1 - j - pad;
    if (raw >= 1 || j == Tc - 1) {
        int r = raw < 0 ? 0 : raw;
        g_xback[b*Tc + r] = x[b*Tc + j];
    }
}

// ---------------- embedding gather -> fp16 ----------------
__global__ void k_gather_h(const int* __restrict__ idx, const float* __restrict__ embed,
                           __half* __restrict__ out) {
    int row = blockIdx.x;
    int e = threadIdx.x;
    float4 v = ((const float4*)(embed + (size_t)idx[row] * Ec))[e];
    ((__half2*)out)[(size_t)row * (Ec/2) + e*2 + 0] = __floats2half2_rn(v.x, v.y);
    ((__half2*)out)[(size_t)row * (Ec/2) + e*2 + 1] = __floats2half2_rn(v.z, v.w);
}

// ======================================================================
// Persistent encoder scan (R10 proven layout): 128 blocks (64/dir, 4 units).
// ======================================================================
__global__ __launch_bounds__(256, 1)
void k_enc_scan(const float* __restrict__ whh_f, const float* __restrict__ whh_b) {
    extern __shared__ float sm[];
    float* wt = sm;                 // [256][16]  (4 gates x 4 units)
    float* sh = sm + 256*16;        // [256][33]  h staged [k][b]
    float* gb = sh + 256*33;        // [16][33]   gates [col][b]

    const int tid  = threadIdx.x;
    const int dir  = blockIdx.x >> 6;
    const int ub   = blockIdx.x & 63;
    const int u0   = ub * 4;
    const float* whh = dir ? whh_b : whh_f;
    const float* pre = dir ? g_encpre_b : g_encpre_f;

    for (int j = tid; j < 16*256; j += 256) {
        int col = j & 15, k = j >> 4;
        int gg = col >> 2, uu = col & 3;
        wt[k*16 + col] = whh[(size_t)(gg*HHc + u0 + uu)*HHc + k];
    }

    const int lane = tid & 31;
    const int c0   = (tid >> 5) * 2;
    const int cb   = tid & 31;
    const int cu   = tid >> 5;
    const bool act = tid < 128;
    const int ug   = dir*HHc + u0 + (act ? cu : 0);
    float creg = 0.f, hsum = 0.f, csum = 0.f;
    __syncthreads();

    for (int t = 0; t < Tc; t++) {
        const float* h_in = &g_ench[t & 1][dir * (Bc*HHc)];
#pragma unroll
        for (int i = 0; i < 8; i++) {
            int idx = tid + i * 256;
            float4 v = __ldcg((const float4*)h_in + idx);
            int j = idx * 4;
            int k = j >> 5, b = j & 31;
            sh[k*33 + b + 0] = v.x; sh[k*33 + b + 1] = v.y;
            sh[k*33 + b + 2] = v.z; sh[k*33 + b + 3] = v.w;
        }
        float pf0 = 0.f, pf1 = 0.f, pf2 = 0.f, pf3 = 0.f;
        if (act) {
            const float* pbt = pre + (size_t)(cb*Tc + t) * (4*HHc) + u0 + cu;
            pf0 = pbt[0*HHc]; pf1 = pbt[1*HHc]; pf2 = pbt[2*HHc]; pf3 = pbt[3*HHc];
        }
        __syncthreads();

        float a0 = 0.f, a1 = 0.f;
#pragma unroll 8
        for (int k = 0; k < 256; k++) {
            float2 w2 = *(const float2*)&wt[k*16 + c0];
            float hv = sh[k*33 + lane];
            a0 += w2.x * hv; a1 += w2.y * hv;
        }
        gb[(c0+0)*33 + lane] = a0;
        gb[(c0+1)*33 + lane] = a1;
        __syncthreads();

        if (act) {
            float gi = gb[(0*4 + cu)*33 + cb] + pf0;
            float gf = gb[(1*4 + cu)*33 + cb] + pf1;
            float gc = gb[(2*4 + cu)*33 + cb] + pf2;
            float go = gb[(3*4 + cu)*33 + cb] + pf3;
            creg = sigm(gf) * creg + sigm(gi) * tanhf(gc);
            float hnew = sigm(go) * tanhf(creg);
            hsum += hnew; csum += creg;
            g_ench[(t+1) & 1][dir*(Bc*HHc) + (u0+cu)*32 + cb] = hnew;
            g_hiddens[(size_t)(cb*Tc + t)*Hc + ug] = hnew;
        }
        gbar(dir, (unsigned)(t + 1), 64, ub);
    }

    if (act) {
        g_dech[0][ug*32 + cb] = hsum * (1.0f / Tc);
        g_decc0[ug*32 + cb]   = csum * (1.0f / Tc);
    }
}

// ======================================================================
// Persistent decoder scan (R10 proven layout): 128 blocks, 4 units each.
// ======================================================================
__global__ __launch_bounds__(256, 1)
void k_dec_scan(const float* __restrict__ whh) {
    extern __shared__ float sm[];
    float* wt = sm;                 // [512][16]
    float* sh = sm + 512*16;        // [512][33]
    float* gb = sh + 512*33;        // [16][33]

    const int tid  = threadIdx.x;
    const int u0   = blockIdx.x * 4;

    for (int j = tid; j < 16*512; j += 256) {
        int col = j & 15, k = j >> 4;
        int gg = col >> 2, uu = col & 3;
        wt[k*16 + col] = whh[(size_t)(gg*Hc + u0 + uu)*Hc + k];
    }

    const int lane = tid & 31;
    const int c0   = (tid >> 5) * 2;
    const int cb   = tid & 31;
    const int cu   = tid >> 5;
    const bool act = tid < 128;
    float creg = 0.f;
    __syncthreads();
    if (act) creg = g_decc0[(u0+cu)*32 + cb];

    for (int ty = 0; ty < TYc; ty++) {
        const float* h_in = &g_dech[ty & 1][0];
#pragma unroll
        for (int i = 0; i < 16; i++) {
            int idx = tid + i * 256;
            float4 v = __ldcg((const float4*)h_in + idx);
            int j = idx * 4;
            int k = j >> 5, b = j & 31;
            sh[k*33 + b + 0] = v.x; sh[k*33 + b + 1] = v.y;
            sh[k*33 + b + 2] = v.z; sh[k*33 + b + 3] = v.w;
        }
        float pf0 = 0.f, pf1 = 0.f, pf2 = 0.f, pf3 = 0.f;
        if (act) {
            const float* pbt = g_decpre + (size_t)(cb*TYc + ty) * (4*Hc) + u0 + cu;
            pf0 = pbt[0*Hc]; pf1 = pbt[1*Hc]; pf2 = pbt[2*Hc]; pf3 = pbt[3*Hc];
        }
        __syncthreads();

        float a0 = 0.f, a1 = 0.f;
#pragma unroll 8
        for (int k = 0; k < 512; k++) {
            float2 w2 = *(const float2*)&wt[k*16 + c0];
            float hv = sh[k*33 + lane];
            a0 += w2.x * hv; a1 += w2.y * hv;
        }
        gb[(c0+0)*33 + lane] = a0;
        gb[(c0+1)*33 + lane] = a1;
        __syncthreads();

        if (act) {
            float gi = gb[(0*4 + cu)*33 + cb] + pf0;
            float gf = gb[(1*4 + cu)*33 + cb] + pf1;
            float gc = gb[(2*4 + cu)*33 + cb] + pf2;
            float go = gb[(3*4 + cu)*33 + cb] + pf3;
            creg = sigm(gf) * creg + sigm(gi) * tanhf(gc);
            float hnew = sigm(go) * tanhf(creg);
            g_dech[(ty+1) & 1][(u0+cu)*32 + cb] = hnew;
            size_t oi = (size_t)(cb*TYc + ty)*(2*Hc) + u0 + cu;
            g_outhid[oi]  = hnew;
            g_outhidh[oi] = __float2half(hnew);
        }
        gbar(2, (unsigned)(ty + 1), 128, blockIdx.x);
    }
}

// ---------------- attention, batch-parallel over (b, ty) ----------------
__global__ __launch_bounds__(256, 1)
void k_attn() {
    const int b  = blockIdx.x;
    const int ty = blockIdx.y;
    const float* h = g_outhid + (size_t)(b*TYc + ty)*(2*Hc);
    __shared__ float hs[Hc];
    __shared__ float sc[Tc];
    __shared__ float red[8];
    for (int i = threadIdx.x; i < Hc; i += 256) hs[i] = h[i];
    __syncthreads();

    const int tp = threadIdx.x >> 1;
    const int half = threadIdx.x & 1;
    const float* hid = g_hiddens + (size_t)(b*Tc + tp)*Hc + half*256;
    const float* hq = hs + half*256;
    float s = 0.f;
#pragma unroll 4
    for (int k = 0; k < 256; k += 4) {
        float4 a = *(const float4*)(hid + k);
        float4 c = *(const float4*)(hq + k);
        s += a.x*c.x + a.y*c.y + a.z*c.z + a.w*c.w;
    }
    s += __shfl_down_sync(0xffffffffu, s, 1);
    if (half == 0) sc[tp] = s;
    __syncthreads();

    const int lane = threadIdx.x & 31, wid = threadIdx.x >> 5;
    float v = (threadIdx.x < Tc) ? sc[threadIdx.x] : -1e30f;
    float m = v;
    for (int o = 16; o; o >>= 1) m = fmaxf(m, __shfl_xor_sync(0xffffffffu, m, o));
    if (!lane) red[wid] = m;
    __syncthreads();
    if (!wid) {
        float xx = (lane < 8) ? red[lane] : -1e30f;
        for (int o = 4; o; o >>= 1) xx = fmaxf(xx, __shfl_xor_sync(0xffffffffu, xx, o));
        if (!lane) red[0] = xx;
    }
    __syncthreads();
    m = red[0];
    float e = (threadIdx.x < Tc) ? expf(v - m) : 0.f;
    float ssum = e;
    for (int o = 16; o; o >>= 1) ssum += __shfl_xor_sync(0xffffffffu, ssum, o);
    __syncthreads();
    if (!lane) red[wid] = ssum;
    __syncthreads();
    if (!wid) {
        float xx = (lane < 8) ? red[lane] : 0.f;
        for (int o = 4; o; o >>= 1) xx += __shfl_xor_sync(0xffffffffu, xx, o);
        if (!lane) red[0] = xx;
    }
    __syncthreads();
    float inv = 1.f / red[0];
    if (threadIdx.x < Tc) sc[threadIdx.x] = e * inv;
    __syncthreads();

    float* octx  = g_outhid  + (size_t)(b*TYc + ty)*(2*Hc) + Hc;
    __half* octh = g_outhidh + (size_t)(b*TYc + ty)*(2*Hc) + Hc;
    for (int d = threadIdx.x; d < Hc; d += 256) {
        float a = 0.f;
#pragma unroll 8
        for (int tq = 0; tq < Tc; tq++) a += sc[tq] * g_hiddens[(size_t)(b*Tc + tq)*Hc + d];
        octx[d] = a;
        octh[d] = __float2half(a);
    }
}

// ---------------- in-place log_softmax (online max+sum) ----------------
__global__ __launch_bounds__(256)
void k_logsoftmax(float* __restrict__ out) {
    const int row = blockIdx.x;
    float* p = out + (size_t)row * Vc;
    __shared__ float redm[8], reds[8];
    const int lane = threadIdx.x & 31, wid = threadIdx.x >> 5;

    float m = -1e30f, s = 0.f;
    for (int i = threadIdx.x; i < Vc; i += 256) {
        float v = p[i];
        if (v > m) { s = s * expf(m - v) + 1.f; m = v; }
        else       s += expf(v - m);
    }
    for (int o = 16; o; o >>= 1) {
        float mo = __shfl_xor_sync(0xffffffffu, m, o);
        float so = __shfl_xor_sync(0xffffffffu, s, o);
        float mn = fmaxf(m, mo);
        s = s * expf(m - mn) + so * expf(mo - mn);
        m = mn;
    }
    if (!lane) { redm[wid] = m; reds[wid] = s; }
    __syncthreads();
    if (!wid) {
        float mm = (lane < 8) ? redm[lane] : -1e30f;
        float ss = (lane < 8) ? reds[lane] : 0.f;
        for (int o = 4; o; o >>= 1) {
            float mo = __shfl_xor_sync(0xffffffffu, mm, o);
            float so = __shfl_xor_sync(0xffffffffu, ss, o);
            float mn = fmaxf(mm, mo);
            ss = ss * expf(mm - mn) + so * expf(mo - mn);
            mm = mn;
        }
        if (!lane) { redm[0] = mm; reds[0] = ss; }
    }
    __syncthreads();
    float lse = redm[0] + logf(reds[0]);
    for (int i = threadIdx.x; i < Vc; i += 256) p[i] -= lse;
}

__global__ void k_copy_tail(float* __restrict__ dst) {
    int i = blockIdx.x * blockDim.x + threadIdx.x;
    if (i < Bc*TYc*2*Hc) dst[i] = g_outhid[i];
}

// ---------------- launch ----------------
extern "C" void kernel_launch(void* const* d_in, const int* in_sizes, int n_in,
                              void* d_out, int out_size) {
    (void)in_sizes; (void)n_in;
    const int*   x      = (const int*)  d_in[0];
    const float* xmask  = (const float*)d_in[1];
    const int*   y      = (const int*)  d_in[2];
    const float* embed  = (const float*)d_in[3];
    const float* w_ih_f = (const float*)d_in[4];
    const float* w_hh_f = (const float*)d_in[5];
    const float* b_ih_f = (const float*)d_in[6];
    const float* b_hh_f = (const float*)d_in[7];
    const float* w_ih_b = (const float*)d_in[8];
    const float* w_hh_b = (const float*)d_in[9];
    const float* b_ih_b = (const float*)d_in[10];
    const float* b_hh_b = (const float*)d_in[11];
    const float* w_ih_d = (const float*)d_in[12];
    const float* w_hh_d = (const float*)d_in[13];
    const float* b_ih_d = (const float*)d_in[14];
    const float* b_hh_d = (const float*)d_in[15];
    const float* W_out  = (const float*)d_in[16];
    const float* b_out  = (const float*)d_in[17];
    float* out = (float*)d_out;

    void *p_xembh, *p_xbembh, *p_yembh, *p_pref, *p_preb, *p_decpre, *p_outhid, *p_outhidh, *p_xback;
    void *p_wf, *p_wb, *p_wd, *p_Wo;
    cudaGetSymbolAddress(&p_xembh,  g_xembh);
    cudaGetSymbolAddress(&p_xbembh, g_xbembh);
    cudaGetSymbolAddress(&p_yembh,  g_yembh);
    cudaGetSymbolAddress(&p_pref,   g_encpre_f);
    cudaGetSymbolAddress(&p_preb,   g_encpre_b);
    cudaGetSymbolAddress(&p_decpre, g_decpre);
    cudaGetSymbolAddress(&p_outhid, g_outhid);
    cudaGetSymbolAddress(&p_outhidh,g_outhidh);
    cudaGetSymbolAddress(&p_xback,  g_xback);
    cudaGetSymbolAddress(&p_wf,     g_wihf_h);
    cudaGetSymbolAddress(&p_wb,     g_wihb_h);
    cudaGetSymbolAddress(&p_wd,     g_wihd_h);
    cudaGetSymbolAddress(&p_Wo,     g_Wouth);

    const int ENC_SMEM  = (256*16 + 256*33 + 16*33) * 4;   //  52,288 B
    const int DEC_SMEM  = (512*16 + 512*33 + 16*33) * 4;   // 102,464 B
    const int GEMM_SMEM = NSTG * STG_HALVES * 2 * 2;       //  61,440 B
    static bool attr_done = false;
    if (!attr_done) {
        cudaFuncSetAttribute(k_enc_scan, cudaFuncAttributeMaxDynamicSharedMemorySize, ENC_SMEM);
        cudaFuncSetAttribute(k_dec_scan, cudaFuncAttributeMaxDynamicSharedMemorySize, DEC_SMEM);
        cudaFuncSetAttribute(k_hmma16,   cudaFuncAttributeMaxDynamicSharedMemorySize, GEMM_SMEM);
        attr_done = true;
    }

    k_init<<<128, 256>>>();
    k_xback<<<Bc, Tc>>>(x, xmask);

    // weight conversions (fp32 -> fp16); small ones ~3us, W_out dominant
    k_f2h<<<(4*HHc*Ec/4 + 255)/256, 256>>>(w_ih_f, (__half*)p_wf, 4*HHc*Ec/4);
    k_f2h<<<(4*HHc*Ec/4 + 255)/256, 256>>>(w_ih_b, (__half*)p_wb, 4*HHc*Ec/4);
    k_f2h<<<(4*Hc*Ec/4  + 255)/256, 256>>>(w_ih_d, (__half*)p_wd, 4*Hc*Ec/4);
    k_f2h<<<(Vc*2*Hc/4  + 255)/256, 256>>>(W_out,  (__half*)p_Wo, Vc*2*Hc/4);

    k_gather_h<<<Bc*Tc, 128>>>(x, embed, (__half*)p_xembh);
    k_gather_h<<<Bc*Tc, 128>>>((const int*)p_xback, embed, (__half*)p_xbembh);
    k_gather_h<<<Bc*TYc, 128>>>(y, embed, (__half*)p_yembh);

    // input-side GEMMs (3-stage fp16 mma)
    k_hmma16<<<dim3((Bc*Tc)/128, (4*HHc)/128), 256, GEMM_SMEM>>>(
        (const __half*)p_xembh,  (const __half*)p_wf, b_ih_f, b_hh_f, (float*)p_pref,   Bc*Tc,  4*HHc, Ec);
    k_hmma16<<<dim3((Bc*Tc)/128, (4*HHc)/128), 256, GEMM_SMEM>>>(
        (const __half*)p_xbembh, (const __half*)p_wb, b_ih_b, b_hh_b, (float*)p_preb,   Bc*Tc,  4*HHc, Ec);
    k_hmma16<<<dim3((Bc*TYc)/128, (4*Hc)/128), 256, GEMM_SMEM>>>(
        (const __half*)p_yembh,  (const __half*)p_wd, b_ih_d, b_hh_d, (float*)p_decpre, Bc*TYc, 4*Hc,  Ec);

    // persistent scans (flag-array grid barriers)
    k_enc_scan<<<128, 256, ENC_SMEM>>>(w_hh_f, w_hh_b);
    k_dec_scan<<<128, 256, DEC_SMEM>>>(w_hh_d);

    // attention
    k_attn<<<dim3(Bc, TYc), 256>>>();

    // projection + log_softmax
    k_hmma16<<<dim3((Bc*TYc)/128, Vc/128), 256, GEMM_SMEM>>>(
        (const __half*)p_outhidh, (const __half*)p_Wo, b_out, nullptr, out, Bc*TYc, Vc, 2*Hc);
    k_logsoftmax<<<Bc*TYc, 256>>>(out);

    long long need = (long long)Bc*TYc*Vc + (long long)Bc*TYc*2*Hc;
    if ((long long)out_size >= need)
        k_copy_tail<<<(Bc*TYc*2*Hc + 255)/256, 256>>>(out + (size_t)Bc*TYc*Vc);
}

// round 16
// speedup vs baseline: 1.1239x; 1.0317x over previous
#include <cuda_runtime.h>
#include <cuda_fp16.h>
#include <math.h>
#include <stdint.h>

// Problem dims
#define Bc  32
#define Tc  128
#define TYc 64
#define Ec  512
#define Hc  512
#define HHc 256
#define Vc  32000

// ---------------- scratch (__device__ globals; no allocations) ----------------
__device__ __half g_xembh [Bc*Tc*Ec];
__device__ __half g_xbembh[Bc*Tc*Ec];
__device__ __half g_yembh [Bc*TYc*Ec];
__device__ int    g_xback [Bc*Tc];
__device__ float  g_encpre_f[Bc*Tc*4*HHc];
__device__ float  g_encpre_b[Bc*Tc*4*HHc];
__device__ float  g_decpre  [Bc*TYc*4*Hc];
__device__ float  g_ench[2][2*Bc*HHc];   // ping-pong h, [pp][dir*8192 + u*32 + b]
__device__ __half g_hiddensh[Bc*Tc*Hc];  // encoder hiddens fp16 [b][t][d]
__device__ float  g_dech[2][Bc*Hc];      // ping-pong decoder h, [pp][u*32 + b]
__device__ float  g_decc0[Bc*Hc];        // decoder c init, [u*32 + b]
__device__ float  g_outhid[Bc*TYc*2*Hc]; // [b][ty][h|ctx] fp32 (for tail copy)
__device__ __half g_outhidh[Bc*TYc*2*Hc];
// fp16 weight copies
__device__ __half g_wihf_h[4*HHc*Ec];
__device__ __half g_wihb_h[4*HHc*Ec];
__device__ __half g_wihd_h[4*Hc*Ec];
__device__ __half g_Wouth [Vc*2*Hc];

// per-block flag barrier state: one 128B line per block, [bar][block*32]
__device__ volatile unsigned g_flags[3][4096];

__device__ __forceinline__ float sigm(float x) { return 1.f / (1.f + expf(-x)); }

// flag-array grid barrier
__device__ __forceinline__ void gbar(int idx, unsigned phase, int nb, int bid) {
    __syncthreads();
    if (threadIdx.x == 0) {
        __threadfence();
        g_flags[idx][bid * 32] = phase;
    }
    if (threadIdx.x < (unsigned)nb) {
        while (g_flags[idx][threadIdx.x * 32] < phase) { }
    }
    __syncthreads();
}

__device__ __forceinline__ uint32_t smem_u32(const void* p) {
    uint32_t a;
    asm("{ .reg .u64 t; cvta.to.shared.u64 t, %1; cvt.u32.u64 %0, t; }" : "=r"(a) : "l"(p));
    return a;
}
__device__ __forceinline__ void ldsm_x4(uint32_t* r, uint32_t addr) {
    asm volatile("ldmatrix.sync.aligned.m8n8.x4.shared.b16 {%0,%1,%2,%3}, [%4];"
        : "=r"(r[0]), "=r"(r[1]), "=r"(r[2]), "=r"(r[3]) : "r"(addr));
}
__device__ __forceinline__ void ldsm_x2(uint32_t* r, uint32_t addr) {
    asm volatile("ldmatrix.sync.aligned.m8n8.x2.shared.b16 {%0,%1}, [%2];"
        : "=r"(r[0]), "=r"(r[1]) : "r"(addr));
}

#define KH 32
#define PH 40
#define NSTG 3
#define STG_HALVES (128 * PH)

__device__ __forceinline__ void mma_f16(float* d, const uint32_t* a, const uint32_t* b) {
    asm volatile(
        "mma.sync.aligned.m16n8k16.row.col.f32.f16.f16.f32 "
        "{%0,%1,%2,%3}, {%4,%5,%6,%7}, {%8,%9}, {%0,%1,%2,%3};\n"
        : "+f"(d[0]), "+f"(d[1]), "+f"(d[2]), "+f"(d[3])
        : "r"(a[0]), "r"(a[1]), "r"(a[2]), "r"(a[3]), "r"(b[0]), "r"(b[1]));
}

// ======================================================================
// fp16 mma.sync GEMM (R15 proven): 3-stage cp.async, 1 sync per stage.
// ======================================================================
__global__ __launch_bounds__(256, 2)
void k_hmma16(const __half* __restrict__ A, const __half* __restrict__ W,
              const float* __restrict__ b1, const float* __restrict__ b2,
              float* __restrict__ C, int M, int N, int K) {
    extern __shared__ __half hsm[];
    __half* sA = hsm;
    __half* sB = hsm + NSTG * STG_HALVES;

    const int tid  = threadIdx.x;
    const int wid  = tid >> 5;
    const int lane = tid & 31;
    const int g    = lane >> 2;
    const int t    = lane & 3;
    const int wm   = (wid & 1) * 64;
    const int wn   = (wid >> 1) * 32;
    const int bm   = blockIdx.x * 128;
    const int bn   = blockIdx.y * 128;

    const __half* Ab = A + (size_t)bm * K;
    const __half* Wb = W + (size_t)bn * K;

    const uint32_t aoff = ((wm + (lane & 15)) * PH + (lane >> 4) * 8) * 2;
    const uint32_t boff = ((wn + (lane & 7)) * PH + ((lane >> 3) & 1) * 8) * 2;
    const uint32_t sAu = smem_u32(sA);
    const uint32_t sBu = smem_u32(sB);

#define LOAD_STAGE(KC0, S) do { \
    _Pragma("unroll") \
    for (int _i = 0; _i < 2; _i++) { \
        int _idx = tid + _i * 256; \
        int _row = _idx >> 2, _seg = _idx & 3; \
        uint32_t _da = sAu + ((S) * STG_HALVES + _row * PH + _seg * 8) * 2; \
        const __half* _sa = Ab + (size_t)_row * K + (KC0) + _seg * 8; \
        asm volatile("cp.async.cg.shared.global [%0], [%1], 16;" :: "r"(_da), "l"(_sa)); \
        uint32_t _db = sBu + ((S) * STG_HALVES + _row * PH + _seg * 8) * 2; \
        const __half* _sb = Wb + (size_t)_row * K + (KC0) + _seg * 8; \
        asm volatile("cp.async.cg.shared.global [%0], [%1], 16;" :: "r"(_db), "l"(_sb)); \
    } \
    asm volatile("cp.async.commit_group;" ::: "memory"); \
} while (0)

    float acc[4][4][4];
#pragma unroll
    for (int i = 0; i < 4; i++)
#pragma unroll
        for (int j = 0; j < 4; j++)
#pragma unroll
            for (int r = 0; r < 4; r++) acc[i][j][r] = 0.f;

    const int NS = K / KH;
    LOAD_STAGE(0, 0);
    LOAD_STAGE(KH, 1);

    int buf = 0;
    for (int s = 0; s < NS; s++) {
        if (s + 1 < NS) asm volatile("cp.async.wait_group 1;" ::: "memory");
        else            asm volatile("cp.async.wait_group 0;" ::: "memory");
        __syncthreads();

        const uint32_t pa = sAu + buf * (STG_HALVES * 2) + aoff;
        const uint32_t pb = sBu + buf * (STG_HALVES * 2) + boff;
#pragma unroll
        for (int ks = 0; ks < 2; ks++) {
            const uint32_t ko = ks * 32;
            uint32_t af[4][4], bf[4][2];
#pragma unroll
            for (int mt = 0; mt < 4; mt++)
                ldsm_x4(af[mt], pa + mt * (16 * PH * 2) + ko);
#pragma unroll
            for (int nt = 0; nt < 4; nt++)
                ldsm_x2(bf[nt], pb + nt * (8 * PH * 2) + ko);
#pragma unroll
            for (int mt = 0; mt < 4; mt++)
#pragma unroll
                for (int nt = 0; nt < 4; nt++)
                    mma_f16(acc[mt][nt], af[mt], bf[nt]);
        }
        if (s + 2 < NS) {
            int nb = buf + 2; if (nb >= NSTG) nb -= NSTG;
            LOAD_STAGE((s + 2) * KH, nb);
        }
        buf = (buf + 1 == NSTG) ? 0 : buf + 1;
    }

#pragma unroll
    for (int nt = 0; nt < 4; nt++) {
        const int n0 = bn + wn + nt * 8 + 2 * t;
        float bb0 = 0.f, bb1 = 0.f;
        if (b1) { bb0 += b1[n0]; bb1 += b1[n0 + 1]; }
        if (b2) { bb0 += b2[n0]; bb1 += b2[n0 + 1]; }
#pragma unroll
        for (int mt = 0; mt < 4; mt++) {
            const int m0 = bm + wm + mt * 16 + g;
            float2 v0 = make_float2(acc[mt][nt][0] + bb0, acc[mt][nt][1] + bb1);
            float2 v1 = make_float2(acc[mt][nt][2] + bb0, acc[mt][nt][3] + bb1);
            *(float2*)(C + (size_t)m0 * N + n0)       = v0;
            *(float2*)(C + (size_t)(m0 + 8) * N + n0) = v1;
        }
    }
#undef LOAD_STAGE
}

// ---------------- fp32 -> fp16 conversion ----------------
__global__ void k_f2h(const float* __restrict__ src, __half* __restrict__ dst, int n4) {
    int i = blockIdx.x * blockDim.x + threadIdx.x;
    if (i < n4) {
        float4 v = ((const float4*)src)[i];
        ((__half2*)dst)[i*2 + 0] = __floats2half2_rn(v.x, v.y);
        ((__half2*)dst)[i*2 + 1] = __floats2half2_rn(v.z, v.w);
    }
}

// ---------------- init ----------------
__global__ void k_init() {
    int i = blockIdx.x * blockDim.x + threadIdx.x;
    if (i < 2*2*Bc*HHc) (&g_ench[0][0])[i] = 0.f;
    if (i < Bc*Tc)      g_xback[i] = 0;
    if (i < 3*4096)     ((unsigned*)g_flags)[i] = 0u;
}

// ---------------- pad-aware reversed tokens ----------------
__global__ void k_xback(const int* __restrict__ x, const float* __restrict__ mask) {
    const int b = blockIdx.x;
    const int j = threadIdx.x;
    __shared__ float red[4];
    float mv = mask[b*Tc + j];
    for (int o = 16; o; o >>= 1) mv += __shfl_xor_sync(0xffffffffu, mv, o);
    if ((threadIdx.x & 31) == 0) red[threadIdx.x >> 5] = mv;
    __syncthreads();
    float s = red[0] + red[1] + red[2] + red[3];
    int pad = Tc - (int)(s + 0.5f);
    int raw = Tc - 1 - j - pad;
    if (raw >= 1 || j == Tc - 1) {
        int r = raw < 0 ? 0 : raw;
        g_xback[b*Tc + r] = x[b*Tc + j];
    }
}

// ---------------- embedding gather -> fp16 ----------------
__global__ void k_gather_h(const int* __restrict__ idx, const float* __restrict__ embed,
                           __half* __restrict__ out) {
    int row = blockIdx.x;
    int e = threadIdx.x;
    float4 v = ((const float4*)(embed + (size_t)idx[row] * Ec))[e];
    ((__half2*)out)[(size_t)row * (Ec/2) + e*2 + 0] = __floats2half2_rn(v.x, v.y);
    ((__half2*)out)[(size_t)row * (Ec/2) + e*2 + 1] = __floats2half2_rn(v.z, v.w);
}

// ======================================================================
// Persistent encoder scan (R10 layout): 128 blocks (64/dir, 4 units).
// Writes fp16 hiddens (sole consumer is the batched attention).
// ======================================================================
__global__ __launch_bounds__(256, 1)
void k_enc_scan(const float* __restrict__ whh_f, const float* __restrict__ whh_b) {
    extern __shared__ float sm[];
    float* wt = sm;                 // [256][16]
    float* sh = sm + 256*16;        // [256][33]
    float* gb = sh + 256*33;        // [16][33]

    const int tid  = threadIdx.x;
    const int dir  = blockIdx.x >> 6;
    const int ub   = blockIdx.x & 63;
    const int u0   = ub * 4;
    const float* whh = dir ? whh_b : whh_f;
    const float* pre = dir ? g_encpre_b : g_encpre_f;

    for (int j = tid; j < 16*256; j += 256) {
        int col = j & 15, k = j >> 4;
        int gg = col >> 2, uu = col & 3;
        wt[k*16 + col] = whh[(size_t)(gg*HHc + u0 + uu)*HHc + k];
    }

    const int lane = tid & 31;
    const int c0   = (tid >> 5) * 2;
    const int cb   = tid & 31;
    const int cu   = tid >> 5;
    const bool act = tid < 128;
    const int ug   = dir*HHc + u0 + (act ? cu : 0);
    float creg = 0.f, hsum = 0.f, csum = 0.f;
    __syncthreads();

    for (int t = 0; t < Tc; t++) {
        const float* h_in = &g_ench[t & 1][dir * (Bc*HHc)];
#pragma unroll
        for (int i = 0; i < 8; i++) {
            int idx = tid + i * 256;
            float4 v = __ldcg((const float4*)h_in + idx);
            int j = idx * 4;
            int k = j >> 5, b = j & 31;
            sh[k*33 + b + 0] = v.x; sh[k*33 + b + 1] = v.y;
            sh[k*33 + b + 2] = v.z; sh[k*33 + b + 3] = v.w;
        }
        float pf0 = 0.f, pf1 = 0.f, pf2 = 0.f, pf3 = 0.f;
        if (act) {
            const float* pbt = pre + (size_t)(cb*Tc + t) * (4*HHc) + u0 + cu;
            pf0 = pbt[0*HHc]; pf1 = pbt[1*HHc]; pf2 = pbt[2*HHc]; pf3 = pbt[3*HHc];
        }
        __syncthreads();

        float a0 = 0.f, a1 = 0.f;
#pragma unroll 8
        for (int k = 0; k < 256; k++) {
            float2 w2 = *(const float2*)&wt[k*16 + c0];
            float hv = sh[k*33 + lane];
            a0 += w2.x * hv; a1 += w2.y * hv;
        }
        gb[(c0+0)*33 + lane] = a0;
        gb[(c0+1)*33 + lane] = a1;
        __syncthreads();

        if (act) {
            float gi = gb[(0*4 + cu)*33 + cb] + pf0;
            float gf = gb[(1*4 + cu)*33 + cb] + pf1;
            float gc = gb[(2*4 + cu)*33 + cb] + pf2;
            float go = gb[(3*4 + cu)*33 + cb] + pf3;
            creg = sigm(gf) * creg + sigm(gi) * tanhf(gc);
            float hnew = sigm(go) * tanhf(creg);
            hsum += hnew; csum += creg;
            g_ench[(t+1) & 1][dir*(Bc*HHc) + (u0+cu)*32 + cb] = hnew;
            g_hiddensh[(size_t)(cb*Tc + t)*Hc + ug] = __float2half(hnew);
        }
        gbar(dir, (unsigned)(t + 1), 64, ub);
    }

    if (act) {
        g_dech[0][ug*32 + cb] = hsum * (1.0f / Tc);
        g_decc0[ug*32 + cb]   = csum * (1.0f / Tc);
    }
}

// ======================================================================
// Persistent decoder scan (R10 layout): 128 blocks, 4 units each.
// ======================================================================
__global__ __launch_bounds__(256, 1)
void k_dec_scan(const float* __restrict__ whh) {
    extern __shared__ float sm[];
    float* wt = sm;                 // [512][16]
    float* sh = sm + 512*16;        // [512][33]
    float* gb = sh + 512*33;        // [16][33]

    const int tid  = threadIdx.x;
    const int u0   = blockIdx.x * 4;

    for (int j = tid; j < 16*512; j += 256) {
        int col = j & 15, k = j >> 4;
        int gg = col >> 2, uu = col & 3;
        wt[k*16 + col] = whh[(size_t)(gg*Hc + u0 + uu)*Hc + k];
    }

    const int lane = tid & 31;
    const int c0   = (tid >> 5) * 2;
    const int cb   = tid & 31;
    const int cu   = tid >> 5;
    const bool act = tid < 128;
    float creg = 0.f;
    __syncthreads();
    if (act) creg = g_decc0[(u0+cu)*32 + cb];

    for (int ty = 0; ty < TYc; ty++) {
        const float* h_in = &g_dech[ty & 1][0];
#pragma unroll
        for (int i = 0; i < 16; i++) {
            int idx = tid + i * 256;
            float4 v = __ldcg((const float4*)h_in + idx);
            int j = idx * 4;
            int k = j >> 5, b = j & 31;
            sh[k*33 + b + 0] = v.x; sh[k*33 + b + 1] = v.y;
            sh[k*33 + b + 2] = v.z; sh[k*33 + b + 3] = v.w;
        }
        float pf0 = 0.f, pf1 = 0.f, pf2 = 0.f, pf3 = 0.f;
        if (act) {
            const float* pbt = g_decpre + (size_t)(cb*TYc + ty) * (4*Hc) + u0 + cu;
            pf0 = pbt[0*Hc]; pf1 = pbt[1*Hc]; pf2 = pbt[2*Hc]; pf3 = pbt[3*Hc];
        }
        __syncthreads();

        float a0 = 0.f, a1 = 0.f;
#pragma unroll 8
        for (int k = 0; k < 512; k++) {
            float2 w2 = *(const float2*)&wt[k*16 + c0];
            float hv = sh[k*33 + lane];
            a0 += w2.x * hv; a1 += w2.y * hv;
        }
        gb[(c0+0)*33 + lane] = a0;
        gb[(c0+1)*33 + lane] = a1;
        __syncthreads();

        if (act) {
            float gi = gb[(0*4 + cu)*33 + cb] + pf0;
            float gf = gb[(1*4 + cu)*33 + cb] + pf1;
            float gc = gb[(2*4 + cu)*33 + cb] + pf2;
            float go = gb[(3*4 + cu)*33 + cb] + pf3;
            creg = sigm(gf) * creg + sigm(gi) * tanhf(gc);
            float hnew = sigm(go) * tanhf(creg);
            g_dech[(ty+1) & 1][(u0+cu)*32 + cb] = hnew;
            size_t oi = (size_t)(cb*TYc + ty)*(2*Hc) + u0 + cu;
            g_outhid[oi]  = hnew;
            g_outhidh[oi] = __float2half(hnew);
        }
        gbar(2, (unsigned)(ty + 1), 128, blockIdx.x);
    }
}

// ======================================================================
// Batched attention: grid (32 b, 2 ty-halves), 512 threads.
// Stage hiddens[b] fp16 in smem ONCE (pitch 258 half2), then each warp
// owns 2 ty rows: scores -> in-warp softmax (registers+shfl) -> ctx.
// ======================================================================
#define HD_PITCH2 258   // half2 per row (256 + 2 pad)
__global__ __launch_bounds__(512, 1)
void k_attn2() {
    extern __shared__ char asmem[];
    __half2* hd = (__half2*)asmem;                           // [128][258]
    float*   sc = (float*)(asmem + Tc * HD_PITCH2 * 4);      // [32][132]

    const int b    = blockIdx.x;
    const int halfb= blockIdx.y;
    const int tid  = threadIdx.x;
    const int wid  = tid >> 5;
    const int lane = tid & 31;

    // stage hiddens[b]: 128 x 256 half2
    const __half2* src = (const __half2*)g_hiddensh + (size_t)b * Tc * (Hc/2);
    for (int i = tid; i < Tc * (Hc/2); i += 512) {
        int t = i >> 8;          // 256 half2 per row
        int r = i & 255;
        hd[t * HD_PITCH2 + r] = src[t * (Hc/2) + r];
    }
    __syncthreads();

    // each warp handles 2 ty rows
#pragma unroll
    for (int yy = 0; yy < 2; yy++) {
        const int r  = wid * 2 + yy;          // local row 0..31
        const int ty = halfb * 32 + r;
        const float* hq = g_outhid + (size_t)(b*TYc + ty) * (2*Hc);  // decoder h

        // scores: lane covers t = lane + 32*i, i<4
        float a[4] = {0.f, 0.f, 0.f, 0.f};
        for (int d0 = 0; d0 < Hc; d0 += 4) {
            float4 q = *(const float4*)(hq + d0);
            const int w0 = d0 >> 1;
#pragma unroll
            for (int i = 0; i < 4; i++) {
                const __half2* hrow = hd + (lane + 32*i) * HD_PITCH2;
                float2 f01 = __half22float2(hrow[w0]);
                float2 f23 = __half22float2(hrow[w0 + 1]);
                a[i] += q.x*f01.x + q.y*f01.y + q.z*f23.x + q.w*f23.y;
            }
        }
        // in-warp softmax over the 128 values (4 per lane)
        float mx = fmaxf(fmaxf(a[0], a[1]), fmaxf(a[2], a[3]));
        for (int o = 16; o; o >>= 1) mx = fmaxf(mx, __shfl_xor_sync(0xffffffffu, mx, o));
        float e0 = expf(a[0]-mx), e1 = expf(a[1]-mx), e2 = expf(a[2]-mx), e3 = expf(a[3]-mx);
        float s = e0 + e1 + e2 + e3;
        for (int o = 16; o; o >>= 1) s += __shfl_xor_sync(0xffffffffu, s, o);
        float inv = 1.f / s;
        float* srow = &sc[r * 132];
        srow[lane +  0] = e0 * inv;
        srow[lane + 32] = e1 * inv;
        srow[lane + 64] = e2 * inv;
        srow[lane + 96] = e3 * inv;
        __syncwarp();

        // ctx: lane covers d-pairs (lane + 32*j), j<8  -> d = 2*(lane+32j)
        float acc[16];
#pragma unroll
        for (int j = 0; j < 16; j++) acc[j] = 0.f;
        for (int t = 0; t < Tc; t++) {
            float av = srow[t];
            const __half2* hrow = hd + t * HD_PITCH2;
#pragma unroll
            for (int j = 0; j < 8; j++) {
                float2 f = __half22float2(hrow[lane + 32*j]);
                acc[2*j]   += av * f.x;
                acc[2*j+1] += av * f.y;
            }
        }
        float*  octx = g_outhid  + (size_t)(b*TYc + ty)*(2*Hc) + Hc;
        __half* octh = g_outhidh + (size_t)(b*TYc + ty)*(2*Hc) + Hc;
#pragma unroll
        for (int j = 0; j < 8; j++) {
            int d = 2 * (lane + 32*j);
            *(float2*)(octx + d)   = make_float2(acc[2*j], acc[2*j+1]);
            *(__half2*)(octh + d)  = __floats2half2_rn(acc[2*j], acc[2*j+1]);
        }
    }
}

// ---------------- in-place log_softmax (online max+sum) ----------------
__global__ __launch_bounds__(256)
void k_logsoftmax(float* __restrict__ out) {
    const int row = blockIdx.x;
    float* p = out + (size_t)row * Vc;
    __shared__ float redm[8], reds[8];
    const int lane = threadIdx.x & 31, wid = threadIdx.x >> 5;

    float m = -1e30f, s = 0.f;
    for (int i = threadIdx.x; i < Vc; i += 256) {
        float v = p[i];
        if (v > m) { s = s * expf(m - v) + 1.f; m = v; }
        else       s += expf(v - m);
    }
    for (int o = 16; o; o >>= 1) {
        float mo = __shfl_xor_sync(0xffffffffu, m, o);
        float so = __shfl_xor_sync(0xffffffffu, s, o);
        float mn = fmaxf(m, mo);
        s = s * expf(m - mn) + so * expf(mo - mn);
        m = mn;
    }
    if (!lane) { redm[wid] = m; reds[wid] = s; }
    __syncthreads();
    if (!wid) {
        float mm = (lane < 8) ? redm[lane] : -1e30f;
        float ss = (lane < 8) ? reds[lane] : 0.f;
        for (int o = 4; o; o >>= 1) {
            float mo = __shfl_xor_sync(0xffffffffu, mm, o);
            float so = __shfl_xor_sync(0xffffffffu, ss, o);
            float mn = fmaxf(mm, mo);
            ss = ss * expf(mm - mn) + so * expf(mo - mn);
            mm = mn;
        }
        if (!lane) { redm[0] = mm; reds[0] = ss; }
    }
    __syncthreads();
    float lse = redm[0] + logf(reds[0]);
    for (int i = threadIdx.x; i < Vc; i += 256) p[i] -= lse;
}

__global__ void k_copy_tail(float* __restrict__ dst) {
    int i = blockIdx.x * blockDim.x + threadIdx.x;
    if (i < Bc*TYc*2*Hc) dst[i] = g_outhid[i];
}

// ---------------- launch ----------------
extern "C" void kernel_launch(void* const* d_in, const int* in_sizes, int n_in,
                              void* d_out, int out_size) {
    (void)in_sizes; (void)n_in;
    const int*   x      = (const int*)  d_in[0];
    const float* xmask  = (const float*)d_in[1];
    const int*   y      = (const int*)  d_in[2];
    const float* embed  = (const float*)d_in[3];
    const float* w_ih_f = (const float*)d_in[4];
    const float* w_hh_f = (const float*)d_in[5];
    const float* b_ih_f = (const float*)d_in[6];
    const float* b_hh_f = (const float*)d_in[7];
    const float* w_ih_b = (const float*)d_in[8];
    const float* w_hh_b = (const float*)d_in[9];
    const float* b_ih_b = (const float*)d_in[10];
    const float* b_hh_b = (const float*)d_in[11];
    const float* w_ih_d = (const float*)d_in[12];
    const float* w_hh_d = (const float*)d_in[13];
    const float* b_ih_d = (const float*)d_in[14];
    const float* b_hh_d = (const float*)d_in[15];
    const float* W_out  = (const float*)d_in[16];
    const float* b_out  = (const float*)d_in[17];
    float* out = (float*)d_out;

    void *p_xembh, *p_xbembh, *p_yembh, *p_pref, *p_preb, *p_decpre, *p_outhid, *p_outhidh, *p_xback;
    void *p_wf, *p_wb, *p_wd, *p_Wo;
    cudaGetSymbolAddress(&p_xembh,  g_xembh);
    cudaGetSymbolAddress(&p_xbembh, g_xbembh);
    cudaGetSymbolAddress(&p_yembh,  g_yembh);
    cudaGetSymbolAddress(&p_pref,   g_encpre_f);
    cudaGetSymbolAddress(&p_preb,   g_encpre_b);
    cudaGetSymbolAddress(&p_decpre, g_decpre);
    cudaGetSymbolAddress(&p_outhid, g_outhid);
    cudaGetSymbolAddress(&p_outhidh,g_outhidh);
    cudaGetSymbolAddress(&p_xback,  g_xback);
    cudaGetSymbolAddress(&p_wf,     g_wihf_h);
    cudaGetSymbolAddress(&p_wb,     g_wihb_h);
    cudaGetSymbolAddress(&p_wd,     g_wihd_h);
    cudaGetSymbolAddress(&p_Wo,     g_Wouth);

    const int ENC_SMEM  = (256*16 + 256*33 + 16*33) * 4;   //  52,288 B
    const int DEC_SMEM  = (512*16 + 512*33 + 16*33) * 4;   // 102,464 B
    const int GEMM_SMEM = NSTG * STG_HALVES * 2 * 2;       //  61,440 B
    const int ATTN_SMEM = Tc * HD_PITCH2 * 4 + 32 * 132 * 4; // 148,992 B
    static bool attr_done = false;
    if (!attr_done) {
        cudaFuncSetAttribute(k_enc_scan, cudaFuncAttributeMaxDynamicSharedMemorySize, ENC_SMEM);
        cudaFuncSetAttribute(k_dec_scan, cudaFuncAttributeMaxDynamicSharedMemorySize, DEC_SMEM);
        cudaFuncSetAttribute(k_hmma16,   cudaFuncAttributeMaxDynamicSharedMemorySize, GEMM_SMEM);
        cudaFuncSetAttribute(k_attn2,    cudaFuncAttributeMaxDynamicSharedMemorySize, ATTN_SMEM);
        attr_done = true;
    }

    k_init<<<128, 256>>>();
    k_xback<<<Bc, Tc>>>(x, xmask);

    // weight conversions (fp32 -> fp16)
    k_f2h<<<(4*HHc*Ec/4 + 255)/256, 256>>>(w_ih_f, (__half*)p_wf, 4*HHc*Ec/4);
    k_f2h<<<(4*HHc*Ec/4 + 255)/256, 256>>>(w_ih_b, (__half*)p_wb, 4*HHc*Ec/4);
    k_f2h<<<(4*Hc*Ec/4  + 255)/256, 256>>>(w_ih_d, (__half*)p_wd, 4*Hc*Ec/4);
    k_f2h<<<(Vc*2*Hc/4  + 255)/256, 256>>>(W_out,  (__half*)p_Wo, Vc*2*Hc/4);

    k_gather_h<<<Bc*Tc, 128>>>(x, embed, (__half*)p_xembh);
    k_gather_h<<<Bc*Tc, 128>>>((const int*)p_xback, embed, (__half*)p_xbembh);
    k_gather_h<<<Bc*TYc, 128>>>(y, embed, (__half*)p_yembh);

    // input-side GEMMs
    k_hmma16<<<dim3((Bc*Tc)/128, (4*HHc)/128), 256, GEMM_SMEM>>>(
        (const __half*)p_xembh,  (const __half*)p_wf, b_ih_f, b_hh_f, (float*)p_pref,   Bc*Tc,  4*HHc, Ec);
    k_hmma16<<<dim3((Bc*Tc)/128, (4*HHc)/128), 256, GEMM_SMEM>>>(
        (const __half*)p_xbembh, (const __half*)p_wb, b_ih_b, b_hh_b, (float*)p_preb,   Bc*Tc,  4*HHc, Ec);
    k_hmma16<<<dim3((Bc*TYc)/128, (4*Hc)/128), 256, GEMM_SMEM>>>(
        (const __half*)p_yembh,  (const __half*)p_wd, b_ih_d, b_hh_d, (float*)p_decpre, Bc*TYc, 4*Hc,  Ec);

    // persistent scans
    k_enc_scan<<<128, 256, ENC_SMEM>>>(w_hh_f, w_hh_b);
    k_dec_scan<<<128, 256, DEC_SMEM>>>(w_hh_d);

    // batched attention (hiddens staged once per (b, half))
    k_attn2<<<dim3(Bc, 2), 512, ATTN_SMEM>>>();

    // projection + log_softmax
    k_hmma16<<<dim3((Bc*TYc)/128, Vc/128), 256, GEMM_SMEM>>>(
        (const __half*)p_outhidh, (const __half*)p_Wo, b_out, nullptr, out, Bc*TYc, Vc, 2*Hc);
    k_logsoftmax<<<Bc*TYc, 256>>>(out);

    long long need = (long long)Bc*TYc*Vc + (long long)Bc*TYc*2*Hc;
    if ((long long)out_size >= need)
        k_copy_tail<<<(Bc*TYc*2*Hc + 255)/256, 256>>>(out + (size_t)Bc*TYc*Vc);
}

// round 17
// speedup vs baseline: 1.4238x; 1.2668x over previous
#include <cuda_runtime.h>
#include <cuda_fp16.h>
#include <math.h>
#include <stdint.h>

// Problem dims
#define Bc  32
#define Tc  128
#define TYc 64
#define Ec  512
#define Hc  512
#define HHc 256
#define Vc  32000

// ---------------- scratch (__device__ globals; no allocations) ----------------
__device__ __half g_xembh [Bc*Tc*Ec];
__device__ __half g_xbembh[Bc*Tc*Ec];
__device__ __half g_yembh [Bc*TYc*Ec];
__device__ int    g_xback [Bc*Tc];
__device__ float  g_encpre_f[Bc*Tc*4*HHc];
__device__ float  g_encpre_b[Bc*Tc*4*HHc];
__device__ float  g_decpre  [Bc*TYc*4*Hc];
__device__ float  g_ench[2][2*Bc*HHc];   // ping-pong h, [pp][dir*8192 + u*32 + b]
__device__ __half g_hiddensh[Bc*Tc*Hc];  // encoder hiddens fp16 [b][t][d]
__device__ float  g_dech[2][Bc*Hc];      // ping-pong decoder h, [pp][u*32 + b]
__device__ float  g_decc0[Bc*Hc];        // decoder c init, [u*32 + b]
__device__ float  g_outhid[Bc*TYc*2*Hc]; // [b][ty][h|ctx] fp32 (for tail copy)
__device__ __half g_outhidh[Bc*TYc*2*Hc];
// fp16 weight copies
__device__ __half g_wihf_h[4*HHc*Ec];
__device__ __half g_wihb_h[4*HHc*Ec];
__device__ __half g_wihd_h[4*Hc*Ec];
__device__ __half g_Wouth [Vc*2*Hc];

// per-block flag barrier state: one 128B line per block, [bar][block*32]
__device__ volatile unsigned g_flags[3][4096];

__device__ __forceinline__ float sigm(float x) { return 1.f / (1.f + expf(-x)); }

// flag-array grid barrier
__device__ __forceinline__ void gbar(int idx, unsigned phase, int nb, int bid) {
    __syncthreads();
    if (threadIdx.x == 0) {
        __threadfence();
        g_flags[idx][bid * 32] = phase;
    }
    if (threadIdx.x < (unsigned)nb) {
        while (g_flags[idx][threadIdx.x * 32] < phase) { }
    }
    __syncthreads();
}

__device__ __forceinline__ uint32_t smem_u32(const void* p) {
    uint32_t a;
    asm("{ .reg .u64 t; cvta.to.shared.u64 t, %1; cvt.u32.u64 %0, t; }" : "=r"(a) : "l"(p));
    return a;
}
__device__ __forceinline__ void ldsm_x4(uint32_t* r, uint32_t addr) {
    asm volatile("ldmatrix.sync.aligned.m8n8.x4.shared.b16 {%0,%1,%2,%3}, [%4];"
        : "=r"(r[0]), "=r"(r[1]), "=r"(r[2]), "=r"(r[3]) : "r"(addr));
}
__device__ __forceinline__ void ldsm_x2(uint32_t* r, uint32_t addr) {
    asm volatile("ldmatrix.sync.aligned.m8n8.x2.shared.b16 {%0,%1}, [%2];"
        : "=r"(r[0]), "=r"(r[1]) : "r"(addr));
}

#define KH 32
#define PH 40
#define NSTG 3
#define STG_HALVES (128 * PH)

__device__ __forceinline__ void mma_f16(float* d, const uint32_t* a, const uint32_t* b) {
    asm volatile(
        "mma.sync.aligned.m16n8k16.row.col.f32.f16.f16.f32 "
        "{%0,%1,%2,%3}, {%4,%5,%6,%7}, {%8,%9}, {%0,%1,%2,%3};\n"
        : "+f"(d[0]), "+f"(d[1]), "+f"(d[2]), "+f"(d[3])
        : "r"(a[0]), "r"(a[1]), "r"(a[2]), "r"(a[3]), "r"(b[0]), "r"(b[1]));
}

// ======================================================================
// fp16 mma.sync GEMM (R15 proven): 3-stage cp.async, 1 sync per stage.
// ======================================================================
__global__ __launch_bounds__(256, 2)
void k_hmma16(const __half* __restrict__ A, const __half* __restrict__ W,
              const float* __restrict__ b1, const float* __restrict__ b2,
              float* __restrict__ C, int M, int N, int K) {
    extern __shared__ __half hsm[];
    __half* sA = hsm;
    __half* sB = hsm + NSTG * STG_HALVES;

    const int tid  = threadIdx.x;
    const int wid  = tid >> 5;
    const int lane = tid & 31;
    const int g    = lane >> 2;
    const int t    = lane & 3;
    const int wm   = (wid & 1) * 64;
    const int wn   = (wid >> 1) * 32;
    const int bm   = blockIdx.x * 128;
    const int bn   = blockIdx.y * 128;

    const __half* Ab = A + (size_t)bm * K;
    const __half* Wb = W + (size_t)bn * K;

    const uint32_t aoff = ((wm + (lane & 15)) * PH + (lane >> 4) * 8) * 2;
    const uint32_t boff = ((wn + (lane & 7)) * PH + ((lane >> 3) & 1) * 8) * 2;
    const uint32_t sAu = smem_u32(sA);
    const uint32_t sBu = smem_u32(sB);

#define LOAD_STAGE(KC0, S) do { \
    _Pragma("unroll") \
    for (int _i = 0; _i < 2; _i++) { \
        int _idx = tid + _i * 256; \
        int _row = _idx >> 2, _seg = _idx & 3; \
        uint32_t _da = sAu + ((S) * STG_HALVES + _row * PH + _seg * 8) * 2; \
        const __half* _sa = Ab + (size_t)_row * K + (KC0) + _seg * 8; \
        asm volatile("cp.async.cg.shared.global [%0], [%1], 16;" :: "r"(_da), "l"(_sa)); \
        uint32_t _db = sBu + ((S) * STG_HALVES + _row * PH + _seg * 8) * 2; \
        const __half* _sb = Wb + (size_t)_row * K + (KC0) + _seg * 8; \
        asm volatile("cp.async.cg.shared.global [%0], [%1], 16;" :: "r"(_db), "l"(_sb)); \
    } \
    asm volatile("cp.async.commit_group;" ::: "memory"); \
} while (0)

    float acc[4][4][4];
#pragma unroll
    for (int i = 0; i < 4; i++)
#pragma unroll
        for (int j = 0; j < 4; j++)
#pragma unroll
            for (int r = 0; r < 4; r++) acc[i][j][r] = 0.f;

    const int NS = K / KH;
    LOAD_STAGE(0, 0);
    LOAD_STAGE(KH, 1);

    int buf = 0;
    for (int s = 0; s < NS; s++) {
        if (s + 1 < NS) asm volatile("cp.async.wait_group 1;" ::: "memory");
        else            asm volatile("cp.async.wait_group 0;" ::: "memory");
        __syncthreads();

        const uint32_t pa = sAu + buf * (STG_HALVES * 2) + aoff;
        const uint32_t pb = sBu + buf * (STG_HALVES * 2) + boff;
#pragma unroll
        for (int ks = 0; ks < 2; ks++) {
            const uint32_t ko = ks * 32;
            uint32_t af[4][4], bf[4][2];
#pragma unroll
            for (int mt = 0; mt < 4; mt++)
                ldsm_x4(af[mt], pa + mt * (16 * PH * 2) + ko);
#pragma unroll
            for (int nt = 0; nt < 4; nt++)
                ldsm_x2(bf[nt], pb + nt * (8 * PH * 2) + ko);
#pragma unroll
            for (int mt = 0; mt < 4; mt++)
#pragma unroll
                for (int nt = 0; nt < 4; nt++)
                    mma_f16(acc[mt][nt], af[mt], bf[nt]);
        }
        if (s + 2 < NS) {
            int nb = buf + 2; if (nb >= NSTG) nb -= NSTG;
            LOAD_STAGE((s + 2) * KH, nb);
        }
        buf = (buf + 1 == NSTG) ? 0 : buf + 1;
    }

#pragma unroll
    for (int nt = 0; nt < 4; nt++) {
        const int n0 = bn + wn + nt * 8 + 2 * t;
        float bb0 = 0.f, bb1 = 0.f;
        if (b1) { bb0 += b1[n0]; bb1 += b1[n0 + 1]; }
        if (b2) { bb0 += b2[n0]; bb1 += b2[n0 + 1]; }
#pragma unroll
        for (int mt = 0; mt < 4; mt++) {
            const int m0 = bm + wm + mt * 16 + g;
            float2 v0 = make_float2(acc[mt][nt][0] + bb0, acc[mt][nt][1] + bb1);
            float2 v1 = make_float2(acc[mt][nt][2] + bb0, acc[mt][nt][3] + bb1);
            *(float2*)(C + (size_t)m0 * N + n0)       = v0;
            *(float2*)(C + (size_t)(m0 + 8) * N + n0) = v1;
        }
    }
#undef LOAD_STAGE
}

// ---------------- fp32 -> fp16 conversion ----------------
__global__ void k_f2h(const float* __restrict__ src, __half* __restrict__ dst, int n4) {
    int i = blockIdx.x * blockDim.x + threadIdx.x;
    if (i < n4) {
        float4 v = ((const float4*)src)[i];
        ((__half2*)dst)[i*2 + 0] = __floats2half2_rn(v.x, v.y);
        ((__half2*)dst)[i*2 + 1] = __floats2half2_rn(v.z, v.w);
    }
}

// ---------------- init ----------------
__global__ void k_init() {
    int i = blockIdx.x * blockDim.x + threadIdx.x;
    if (i < 2*2*Bc*HHc) (&g_ench[0][0])[i] = 0.f;
    if (i < Bc*Tc)      g_xback[i] = 0;
    if (i < 3*4096)     ((unsigned*)g_flags)[i] = 0u;
}

// ---------------- pad-aware reversed tokens ----------------
__global__ void k_xback(const int* __restrict__ x, const float* __restrict__ mask) {
    const int b = blockIdx.x;
    const int j = threadIdx.x;
    __shared__ float red[4];
    float mv = mask[b*Tc + j];
    for (int o = 16; o; o >>= 1) mv += __shfl_xor_sync(0xffffffffu, mv, o);
    if ((threadIdx.x & 31) == 0) red[threadIdx.x >> 5] = mv;
    __syncthreads();
    float s = red[0] + red[1] + red[2] + red[3];
    int pad = Tc - (int)(s + 0.5f);
    int raw = Tc - 1 - j - pad;
    if (raw >= 1 || j == Tc - 1) {
        int r = raw < 0 ? 0 : raw;
        g_xback[b*Tc + r] = x[b*Tc + j];
    }
}

// ---------------- embedding gather -> fp16 ----------------
__global__ void k_gather_h(const int* __restrict__ idx, const float* __restrict__ embed,
                           __half* __restrict__ out) {
    int row = blockIdx.x;
    int e = threadIdx.x;
    float4 v = ((const float4*)(embed + (size_t)idx[row] * Ec))[e];
    ((__half2*)out)[(size_t)row * (Ec/2) + e*2 + 0] = __floats2half2_rn(v.x, v.y);
    ((__half2*)out)[(size_t)row * (Ec/2) + e*2 + 1] = __floats2half2_rn(v.z, v.w);
}

// ======================================================================
// Tensor-core encoder scan: 128 blocks (64/dir, 4 units = 16 gate-cols).
// Per step: stage h fp16 [b][k] -> 8 warps x (K-slice 32) mma -> partial
// reduce -> cell. B-frags (weights) preloaded in registers once.
// ======================================================================
#define PKE 264
#define PPITCH 26
__global__ __launch_bounds__(256, 1)
void k_enc_scan(const float* __restrict__ whh_f, const float* __restrict__ whh_b) {
    extern __shared__ char esm[];
    __half* wh   = (__half*)esm;                       // [16][PKE]
    __half* hh   = (__half*)(esm + 16*PKE*2);          // [32][PKE]
    float*  part = (float*)(esm + (16+32)*PKE*2);      // [8][32][PPITCH]

    const int tid  = threadIdx.x;
    const int wid  = tid >> 5;
    const int lane = tid & 31;
    const int dir  = blockIdx.x >> 6;
    const int ub   = blockIdx.x & 63;
    const int u0   = ub * 4;
    const float* whh = dir ? whh_b : whh_f;
    const float* pre = dir ? g_encpre_b : g_encpre_f;

    // weights -> fp16 smem [col][k], col = gate*4 + unit
    for (int j = tid; j < 16*256; j += 256) {
        int col = j >> 8, k = j & 255;
        int gg = col >> 2, uu = col & 3;
        wh[col*PKE + k] = __float2half(whh[(size_t)(gg*HHc + u0 + uu)*HHc + k]);
    }
    __syncthreads();

    const int kbase = wid * 32;                  // K-slice per warp
    const uint32_t whu = smem_u32(wh);
    const uint32_t hhu = smem_u32(hh);
    uint32_t bf[2][2][2];                        // [kc][nt][reg], preloaded once
#pragma unroll
    for (int kc = 0; kc < 2; kc++)
#pragma unroll
        for (int nt = 0; nt < 2; nt++)
            ldsm_x2(bf[kc][nt],
                whu + ((nt*8 + (lane&7))*PKE + kbase + kc*16 + ((lane>>3)&1)*8) * 2);

    const int cb = tid & 31;
    const int cu = (tid >> 5) & 3;
    const bool act = tid < 128;
    const int ug = dir*HHc + u0 + cu;
    const uint32_t aoff = ((lane & 15)*PKE + kbase + (lane>>4)*8) * 2;
    float creg = 0.f, hsum = 0.f, csum = 0.f;

    for (int t = 0; t < Tc; t++) {
        const float* h_in = &g_ench[t & 1][dir * (Bc*HHc)];
#pragma unroll
        for (int i = 0; i < 8; i++) {
            int idx = tid + i * 256;             // float4 index < 2048
            float4 v = __ldcg((const float4*)h_in + idx);
            int j = idx * 4;
            int u = j >> 5, b = j & 31;          // element = u*32 + b
            hh[(b+0)*PKE + u] = __float2half(v.x);
            hh[(b+1)*PKE + u] = __float2half(v.y);
            hh[(b+2)*PKE + u] = __float2half(v.z);
            hh[(b+3)*PKE + u] = __float2half(v.w);
        }
        float pf0 = 0.f, pf1 = 0.f, pf2 = 0.f, pf3 = 0.f;
        if (act) {
            const float* pbt = pre + (size_t)(cb*Tc + t) * (4*HHc) + u0 + cu;
            pf0 = pbt[0*HHc]; pf1 = pbt[1*HHc]; pf2 = pbt[2*HHc]; pf3 = pbt[3*HHc];
        }
        __syncthreads();

        float acc[2][2][4];
#pragma unroll
        for (int i = 0; i < 2; i++)
#pragma unroll
            for (int j = 0; j < 2; j++)
#pragma unroll
                for (int r = 0; r < 4; r++) acc[i][j][r] = 0.f;
#pragma unroll
        for (int kc = 0; kc < 2; kc++) {
            uint32_t af0[4], af1[4];
            ldsm_x4(af0, hhu + aoff + kc*32);
            ldsm_x4(af1, hhu + aoff + (16*PKE)*2 + kc*32);
            mma_f16(acc[0][0], af0, bf[kc][0]);
            mma_f16(acc[0][1], af0, bf[kc][1]);
            mma_f16(acc[1][0], af1, bf[kc][0]);
            mma_f16(acc[1][1], af1, bf[kc][1]);
        }
        // store partials: part[wid][m][n]
        {
            const int g = lane >> 2, t2 = (lane & 3) * 2;
            float* pw = part + (wid*32) * PPITCH;
#pragma unroll
            for (int mt = 0; mt < 2; mt++)
#pragma unroll
                for (int nt = 0; nt < 2; nt++) {
                    *(float2*)(pw + (mt*16+g  )*PPITCH + nt*8 + t2) =
                        make_float2(acc[mt][nt][0], acc[mt][nt][1]);
                    *(float2*)(pw + (mt*16+g+8)*PPITCH + nt*8 + t2) =
                        make_float2(acc[mt][nt][2], acc[mt][nt][3]);
                }
        }
        __syncthreads();

        if (act) {
            float gi = pf0, gf = pf1, gc = pf2, go = pf3;
#pragma unroll
            for (int w = 0; w < 8; w++) {
                const float* pp = part + (w*32 + cb) * PPITCH;
                gi += pp[0*4 + cu]; gf += pp[1*4 + cu];
                gc += pp[2*4 + cu]; go += pp[3*4 + cu];
            }
            creg = sigm(gf) * creg + sigm(gi) * tanhf(gc);
            float hnew = sigm(go) * tanhf(creg);
            hsum += hnew; csum += creg;
            g_ench[(t+1) & 1][dir*(Bc*HHc) + (u0+cu)*32 + cb] = hnew;
            g_hiddensh[(size_t)(cb*Tc + t)*Hc + ug] = __float2half(hnew);
        }
        gbar(dir, (unsigned)(t + 1), 64, ub);
    }

    if (act) {
        g_dech[0][ug*32 + cb] = hsum * (1.0f / Tc);
        g_decc0[ug*32 + cb]   = csum * (1.0f / Tc);
    }
}

// ======================================================================
// Tensor-core decoder scan: 128 blocks, 4 units each, K=512.
// ======================================================================
#define PKD 520
__global__ __launch_bounds__(256, 1)
void k_dec_scan(const float* __restrict__ whh) {
    extern __shared__ char dsm[];
    __half* wh   = (__half*)dsm;                       // [16][PKD]
    __half* hh   = (__half*)(dsm + 16*PKD*2);          // [32][PKD]
    float*  part = (float*)(dsm + (16+32)*PKD*2);      // [8][32][PPITCH]

    const int tid  = threadIdx.x;
    const int wid  = tid >> 5;
    const int lane = tid & 31;
    const int u0   = blockIdx.x * 4;

    for (int j = tid; j < 16*512; j += 256) {
        int col = j >> 9, k = j & 511;
        int gg = col >> 2, uu = col & 3;
        wh[col*PKD + k] = __float2half(whh[(size_t)(gg*Hc + u0 + uu)*Hc + k]);
    }
    __syncthreads();

    const int kbase = wid * 64;
    const uint32_t whu = smem_u32(wh);
    const uint32_t hhu = smem_u32(hh);
    uint32_t bf[4][2][2];
#pragma unroll
    for (int kc = 0; kc < 4; kc++)
#pragma unroll
        for (int nt = 0; nt < 2; nt++)
            ldsm_x2(bf[kc][nt],
                whu + ((nt*8 + (lane&7))*PKD + kbase + kc*16 + ((lane>>3)&1)*8) * 2);

    const int cb = tid & 31;
    const int cu = (tid >> 5) & 3;
    const bool act = tid < 128;
    const uint32_t aoff = ((lane & 15)*PKD + kbase + (lane>>4)*8) * 2;
    float creg = 0.f;
    if (act) creg = g_decc0[(u0+cu)*32 + cb];

    for (int ty = 0; ty < TYc; ty++) {
        const float* h_in = &g_dech[ty & 1][0];
#pragma unroll
        for (int i = 0; i < 16; i++) {
            int idx = tid + i * 256;             // float4 index < 4096
            float4 v = __ldcg((const float4*)h_in + idx);
            int j = idx * 4;
            int u = j >> 5, b = j & 31;
            hh[(b+0)*PKD + u] = __float2half(v.x);
            hh[(b+1)*PKD + u] = __float2half(v.y);
            hh[(b+2)*PKD + u] = __float2half(v.z);
            hh[(b+3)*PKD + u] = __float2half(v.w);
        }
        float pf0 = 0.f, pf1 = 0.f, pf2 = 0.f, pf3 = 0.f;
        if (act) {
            const float* pbt = g_decpre + (size_t)(cb*TYc + ty) * (4*Hc) + u0 + cu;
            pf0 = pbt[0*Hc]; pf1 = pbt[1*Hc]; pf2 = pbt[2*Hc]; pf3 = pbt[3*Hc];
        }
        __syncthreads();

        float acc[2][2][4];
#pragma unroll
        for (int i = 0; i < 2; i++)
#pragma unroll
            for (int j = 0; j < 2; j++)
#pragma unroll
                for (int r = 0; r < 4; r++) acc[i][j][r] = 0.f;
#pragma unroll
        for (int kc = 0; kc < 4; kc++) {
            uint32_t af0[4], af1[4];
            ldsm_x4(af0, hhu + aoff + kc*32);
            ldsm_x4(af1, hhu + aoff + (16*PKD)*2 + kc*32);
            mma_f16(acc[0][0], af0, bf[kc][0]);
            mma_f16(acc[0][1], af0, bf[kc][1]);
            mma_f16(acc[1][0], af1, bf[kc][0]);
            mma_f16(acc[1][1], af1, bf[kc][1]);
        }
        {
            const int g = lane >> 2, t2 = (lane & 3) * 2;
            float* pw = part + (wid*32) * PPITCH;
#pragma unroll
            for (int mt = 0; mt < 2; mt++)
#pragma unroll
                for (int nt = 0; nt < 2; nt++) {
                    *(float2*)(pw + (mt*16+g  )*PPITCH + nt*8 + t2) =
                        make_float2(acc[mt][nt][0], acc[mt][nt][1]);
                    *(float2*)(pw + (mt*16+g+8)*PPITCH + nt*8 + t2) =
                        make_float2(acc[mt][nt][2], acc[mt][nt][3]);
                }
        }
        __syncthreads();

        if (act) {
            float gi = pf0, gf = pf1, gc = pf2, go = pf3;
#pragma unroll
            for (int w = 0; w < 8; w++) {
                const float* pp = part + (w*32 + cb) * PPITCH;
                gi += pp[0*4 + cu]; gf += pp[1*4 + cu];
                gc += pp[2*4 + cu]; go += pp[3*4 + cu];
            }
            creg = sigm(gf) * creg + sigm(gi) * tanhf(gc);
            float hnew = sigm(go) * tanhf(creg);
            g_dech[(ty+1) & 1][(u0+cu)*32 + cb] = hnew;
            size_t oi = (size_t)(cb*TYc + ty)*(2*Hc) + u0 + cu;
            g_outhid[oi]  = hnew;
            g_outhidh[oi] = __float2half(hnew);
        }
        gbar(2, (unsigned)(ty + 1), 128, blockIdx.x);
    }
}

// ======================================================================
// Batched attention (R16 proven): grid (32 b, 2 halves), 512 threads.
// ======================================================================
#define HD_PITCH2 258
__global__ __launch_bounds__(512, 1)
void k_attn2() {
    extern __shared__ char asmem[];
    __half2* hd = (__half2*)asmem;                           // [128][258]
    float*   sc = (float*)(asmem + Tc * HD_PITCH2 * 4);      // [32][132]

    const int b    = blockIdx.x;
    const int halfb= blockIdx.y;
    const int tid  = threadIdx.x;
    const int wid  = tid >> 5;
    const int lane = tid & 31;

    const __half2* src = (const __half2*)g_hiddensh + (size_t)b * Tc * (Hc/2);
    for (int i = tid; i < Tc * (Hc/2); i += 512) {
        int t = i >> 8;
        int r = i & 255;
        hd[t * HD_PITCH2 + r] = src[t * (Hc/2) + r];
    }
    __syncthreads();

#pragma unroll
    for (int yy = 0; yy < 2; yy++) {
        const int r  = wid * 2 + yy;
        const int ty = halfb * 32 + r;
        const float* hq = g_outhid + (size_t)(b*TYc + ty) * (2*Hc);

        float a[4] = {0.f, 0.f, 0.f, 0.f};
        for (int d0 = 0; d0 < Hc; d0 += 4) {
            float4 q = *(const float4*)(hq + d0);
            const int w0 = d0 >> 1;
#pragma unroll
            for (int i = 0; i < 4; i++) {
                const __half2* hrow = hd + (lane + 32*i) * HD_PITCH2;
                float2 f01 = __half22float2(hrow[w0]);
                float2 f23 = __half22float2(hrow[w0 + 1]);
                a[i] += q.x*f01.x + q.y*f01.y + q.z*f23.x + q.w*f23.y;
            }
        }
        float mx = fmaxf(fmaxf(a[0], a[1]), fmaxf(a[2], a[3]));
        for (int o = 16; o; o >>= 1) mx = fmaxf(mx, __shfl_xor_sync(0xffffffffu, mx, o));
        float e0 = expf(a[0]-mx), e1 = expf(a[1]-mx), e2 = expf(a[2]-mx), e3 = expf(a[3]-mx);
        float s = e0 + e1 + e2 + e3;
        for (int o = 16; o; o >>= 1) s += __shfl_xor_sync(0xffffffffu, s, o);
        float inv = 1.f / s;
        float* srow = &sc[r * 132];
        srow[lane +  0] = e0 * inv;
        srow[lane + 32] = e1 * inv;
        srow[lane + 64] = e2 * inv;
        srow[lane + 96] = e3 * inv;
        __syncwarp();

        float acc[16];
#pragma unroll
        for (int j = 0; j < 16; j++) acc[j] = 0.f;
        for (int t = 0; t < Tc; t++) {
            float av = srow[t];
            const __half2* hrow = hd + t * HD_PITCH2;
#pragma unroll
            for (int j = 0; j < 8; j++) {
                float2 f = __half22float2(hrow[lane + 32*j]);
                acc[2*j]   += av * f.x;
                acc[2*j+1] += av * f.y;
            }
        }
        float*  octx = g_outhid  + (size_t)(b*TYc + ty)*(2*Hc) + Hc;
        __half* octh = g_outhidh + (size_t)(b*TYc + ty)*(2*Hc) + Hc;
#pragma unroll
        for (int j = 0; j < 8; j++) {
            int d = 2 * (lane + 32*j);
            *(float2*)(octx + d)   = make_float2(acc[2*j], acc[2*j+1]);
            *(__half2*)(octh + d)  = __floats2half2_rn(acc[2*j], acc[2*j+1]);
        }
    }
}

// ---------------- in-place log_softmax (online max+sum) ----------------
__global__ __launch_bounds__(256)
void k_logsoftmax(float* __restrict__ out) {
    const int row = blockIdx.x;
    float* p = out + (size_t)row * Vc;
    __shared__ float redm[8], reds[8];
    const int lane = threadIdx.x & 31, wid = threadIdx.x >> 5;

    float m = -1e30f, s = 0.f;
    for (int i = threadIdx.x; i < Vc; i += 256) {
        float v = p[i];
        if (v > m) { s = s * expf(m - v) + 1.f; m = v; }
        else       s += expf(v - m);
    }
    for (int o = 16; o; o >>= 1) {
        float mo = __shfl_xor_sync(0xffffffffu, m, o);
        float so = __shfl_xor_sync(0xffffffffu, s, o);
        float mn = fmaxf(m, mo);
        s = s * expf(m - mn) + so * expf(mo - mn);
        m = mn;
    }
    if (!lane) { redm[wid] = m; reds[wid] = s; }
    __syncthreads();
    if (!wid) {
        float mm = (lane < 8) ? redm[lane] : -1e30f;
        float ss = (lane < 8) ? reds[lane] : 0.f;
        for (int o = 4; o; o >>= 1) {
            float mo = __shfl_xor_sync(0xffffffffu, mm, o);
            float so = __shfl_xor_sync(0xffffffffu, ss, o);
            float mn = fmaxf(mm, mo);
            ss = ss * expf(mm - mn) + so * expf(mo - mn);
            mm = mn;
        }
        if (!lane) { redm[0] = mm; reds[0] = ss; }
    }
    __syncthreads();
    float lse = redm[0] + logf(reds[0]);
    for (int i = threadIdx.x; i < Vc; i += 256) p[i] -= lse;
}

__global__ void k_copy_tail(float* __restrict__ dst) {
    int i = blockIdx.x * blockDim.x + threadIdx.x;
    if (i < Bc*TYc*2*Hc) dst[i] = g_outhid[i];
}

// ---------------- launch ----------------
extern "C" void kernel_launch(void* const* d_in, const int* in_sizes, int n_in,
                              void* d_out, int out_size) {
    (void)in_sizes; (void)n_in;
    const int*   x      = (const int*)  d_in[0];
    const float* xmask  = (const float*)d_in[1];
    const int*   y      = (const int*)  d_in[2];
    const float* embed  = (const float*)d_in[3];
    const float* w_ih_f = (const float*)d_in[4];
    const float* w_hh_f = (const float*)d_in[5];
    const float* b_ih_f = (const float*)d_in[6];
    const float* b_hh_f = (const float*)d_in[7];
    const float* w_ih_b = (const float*)d_in[8];
    const float* w_hh_b = (const float*)d_in[9];
    const float* b_ih_b = (const float*)d_in[10];
    const float* b_hh_b = (const float*)d_in[11];
    const float* w_ih_d = (const float*)d_in[12];
    const float* w_hh_d = (const float*)d_in[13];
    const float* b_ih_d = (const float*)d_in[14];
    const float* b_hh_d = (const float*)d_in[15];
    const float* W_out  = (const float*)d_in[16];
    const float* b_out  = (const float*)d_in[17];
    float* out = (float*)d_out;

    void *p_xembh, *p_xbembh, *p_yembh, *p_pref, *p_preb, *p_decpre, *p_outhid, *p_outhidh, *p_xback;
    void *p_wf, *p_wb, *p_wd, *p_Wo;
    cudaGetSymbolAddress(&p_xembh,  g_xembh);
    cudaGetSymbolAddress(&p_xbembh, g_xbembh);
    cudaGetSymbolAddress(&p_yembh,  g_yembh);
    cudaGetSymbolAddress(&p_pref,   g_encpre_f);
    cudaGetSymbolAddress(&p_preb,   g_encpre_b);
    cudaGetSymbolAddress(&p_decpre, g_decpre);
    cudaGetSymbolAddress(&p_outhid, g_outhid);
    cudaGetSymbolAddress(&p_outhidh,g_outhidh);
    cudaGetSymbolAddress(&p_xback,  g_xback);
    cudaGetSymbolAddress(&p_wf,     g_wihf_h);
    cudaGetSymbolAddress(&p_wb,     g_wihb_h);
    cudaGetSymbolAddress(&p_wd,     g_wihd_h);
    cudaGetSymbolAddress(&p_Wo,     g_Wouth);

    const int ENC_SMEM  = (16+32)*PKE*2 + 8*32*PPITCH*4;   // 25344 + 26624 = 51,968 B
    const int DEC_SMEM  = (16+32)*PKD*2 + 8*32*PPITCH*4;   // 49920 + 26624 = 76,544 B
    const int GEMM_SMEM = NSTG * STG_HALVES * 2 * 2;       //  61,440 B
    const int ATTN_SMEM = Tc * HD_PITCH2 * 4 + 32 * 132 * 4; // 148,992 B
    static bool attr_done = false;
    if (!attr_done) {
        cudaFuncSetAttribute(k_enc_scan, cudaFuncAttributeMaxDynamicSharedMemorySize, ENC_SMEM);
        cudaFuncSetAttribute(k_dec_scan, cudaFuncAttributeMaxDynamicSharedMemorySize, DEC_SMEM);
        cudaFuncSetAttribute(k_hmma16,   cudaFuncAttributeMaxDynamicSharedMemorySize, GEMM_SMEM);
        cudaFuncSetAttribute(k_attn2,    cudaFuncAttributeMaxDynamicSharedMemorySize, ATTN_SMEM);
        attr_done = true;
    }

    k_init<<<128, 256>>>();
    k_xback<<<Bc, Tc>>>(x, xmask);

    // weight conversions (fp32 -> fp16)
    k_f2h<<<(4*HHc*Ec/4 + 255)/256, 256>>>(w_ih_f, (__half*)p_wf, 4*HHc*Ec/4);
    k_f2h<<<(4*HHc*Ec/4 + 255)/256, 256>>>(w_ih_b, (__half*)p_wb, 4*HHc*Ec/4);
    k_f2h<<<(4*Hc*Ec/4  + 255)/256, 256>>>(w_ih_d, (__half*)p_wd, 4*Hc*Ec/4);
    k_f2h<<<(Vc*2*Hc/4  + 255)/256, 256>>>(W_out,  (__half*)p_Wo, Vc*2*Hc/4);

    k_gather_h<<<Bc*Tc, 128>>>(x, embed, (__half*)p_xembh);
    k_gather_h<<<Bc*Tc, 128>>>((const int*)p_xback, embed, (__half*)p_xbembh);
    k_gather_h<<<Bc*TYc, 128>>>(y, embed, (__half*)p_yembh);

    // input-side GEMMs
    k_hmma16<<<dim3((Bc*Tc)/128, (4*HHc)/128), 256, GEMM_SMEM>>>(
        (const __half*)p_xembh,  (const __half*)p_wf, b_ih_f, b_hh_f, (float*)p_pref,   Bc*Tc,  4*HHc, Ec);
    k_hmma16<<<dim3((Bc*Tc)/128, (4*HHc)/128), 256, GEMM_SMEM>>>(
        (const __half*)p_xbembh, (const __half*)p_wb, b_ih_b, b_hh_b, (float*)p_preb,   Bc*Tc,  4*HHc, Ec);
    k_hmma16<<<dim3((Bc*TYc)/128, (4*Hc)/128), 256, GEMM_SMEM>>>(
        (const __half*)p_yembh,  (const __half*)p_wd, b_ih_d, b_hh_d, (float*)p_decpre, Bc*TYc, 4*Hc,  Ec);

    // persistent scans (tensor-core gate GEMMs)
    k_enc_scan<<<128, 256, ENC_SMEM>>>(w_hh_f, w_hh_b);
    k_dec_scan<<<128, 256, DEC_SMEM>>>(w_hh_d);

    // batched attention
    k_attn2<<<dim3(Bc, 2), 512, ATTN_SMEM>>>();

    // projection + log_softmax
    k_hmma16<<<dim3((Bc*TYc)/128, Vc/128), 256, GEMM_SMEM>>>(
        (const __half*)p_outhidh, (const __half*)p_Wo, b_out, nullptr, out, Bc*TYc, Vc, 2*Hc);
    k_logsoftmax<<<Bc*TYc, 256>>>(out);

    long long need = (long long)Bc*TYc*Vc + (long long)Bc*TYc*2*Hc;
    if ((long long)out_size >= need)
        k_copy_tail<<<(Bc*TYc*2*Hc + 255)/256, 256>>>(out + (size_t)Bc*TYc*Vc);
}